// round 3
// baseline (speedup 1.0000x reference)
#include <cuda_runtime.h>
#include <math.h>

#define SEQ 4096
#define DM  768
#define NH  12
#define DH  64
#define FF  3072
#define NE  7
#define WIN 256
#define CAP 4096

// ---------------- scratch (static device globals; no allocation) ----------------
__device__ float g_q[NH * SEQ * DH];
__device__ float g_k[NH * SEQ * DH];
__device__ float g_v[NH * SEQ * DH];
__device__ float g_attno[SEQ * DM];
__device__ float g_tmp[SEQ * DM];
__device__ float g_x1[SEQ * DM];
__device__ float g_moe[SEQ * DM];
__device__ float g_h[NE * CAP * FF];     // 352 MB
__device__ float g_eo[NE * CAP * DM];    // 88 MB
__device__ int   g_cnt[NE];
__device__ int   g_tok[NE * CAP];
__device__ float g_wl[NE * CAP];
__device__ int   g_pos[SEQ * 2];

// ---------------- reset ----------------
__global__ void reset_kernel() {
    if (threadIdx.x < NE) g_cnt[threadIdx.x] = 0;
}

// ---------------- generic tiled fp32 GEMM ----------------
// C[M,N] = A[M,K] @ B[K,N] (+bias) with epilogue modes:
//  mode 0: C[row*N+col] = acc + bias[col]
//  mode 1: QKV scatter:  C[((col>>6)*M + row)*64 + (col&63)] = (acc+bias[col])*scale
//  mode 2: C[row*N+col] = acc + bias[col] + residual[row*N+col]
#define BM 128
#define BN 64
#define BK 16

__global__ __launch_bounds__(256) void gemm_kernel(
    const float* __restrict__ A, const float* __restrict__ B,
    const float* __restrict__ bias, float* __restrict__ C,
    int M, int N, int K, const float* __restrict__ residual,
    float scale, int mode)
{
    __shared__ float As[BK][BM];
    __shared__ float Bs[BK][BN];
    int tid = threadIdx.x;
    int m0 = blockIdx.y * BM;
    int n0 = blockIdx.x * BN;
    int rg = tid >> 4;          // 0..15 -> rows rg*8..+7
    int cg = tid & 15;          // cols cg*4..+3
    int ar = tid >> 2;          // 0..63
    int ac = (tid & 3) << 2;    // 0,4,8,12
    int br = tid >> 4;          // 0..15
    int bc = (tid & 15) << 2;   // 0..60

    float acc[8][4];
#pragma unroll
    for (int i = 0; i < 8; i++)
#pragma unroll
        for (int j = 0; j < 4; j++) acc[i][j] = 0.f;

    for (int k0 = 0; k0 < K; k0 += BK) {
#pragma unroll
        for (int it = 0; it < 2; it++) {
            int r = ar + it * 64;
            float4 av = *(const float4*)&A[(size_t)(m0 + r) * K + k0 + ac];
            As[ac + 0][r] = av.x;
            As[ac + 1][r] = av.y;
            As[ac + 2][r] = av.z;
            As[ac + 3][r] = av.w;
        }
        float4 bv = *(const float4*)&B[(size_t)(k0 + br) * N + n0 + bc];
        *(float4*)&Bs[br][bc] = bv;
        __syncthreads();
#pragma unroll
        for (int k = 0; k < BK; k++) {
            float4 a0 = *(const float4*)&As[k][rg * 8];
            float4 a1 = *(const float4*)&As[k][rg * 8 + 4];
            float4 b0 = *(const float4*)&Bs[k][cg * 4];
            float a[8] = {a0.x, a0.y, a0.z, a0.w, a1.x, a1.y, a1.z, a1.w};
            float b[4] = {b0.x, b0.y, b0.z, b0.w};
#pragma unroll
            for (int i = 0; i < 8; i++)
#pragma unroll
                for (int j = 0; j < 4; j++) acc[i][j] += a[i] * b[j];
        }
        __syncthreads();
    }

#pragma unroll
    for (int i = 0; i < 8; i++) {
        int row = m0 + rg * 8 + i;
#pragma unroll
        for (int j = 0; j < 4; j++) {
            int col = n0 + cg * 4 + j;
            float v = acc[i][j] + bias[col];
            if (mode == 0) {
                C[(size_t)row * N + col] = v;
            } else if (mode == 1) {
                C[((size_t)(col >> 6) * M + row) * 64 + (col & 63)] = v * scale;
            } else {
                C[(size_t)row * N + col] = v + residual[(size_t)row * N + col];
            }
        }
    }
}

// ---------------- MoE grouped GEMM 1: x1(gather) @ W1e + b1e -> GELU -> g_h ----------------
__global__ __launch_bounds__(256) void moe_gemm1_kernel(
    const float* __restrict__ X, const float* __restrict__ W1,
    const float* __restrict__ b1)
{
    int e = blockIdx.z;
    int M = g_cnt[e];
    int m0 = blockIdx.y * BM;
    if (m0 >= M) return;
    const float* B = W1 + (size_t)e * DM * FF;
    const float* bias = b1 + (size_t)e * FF;
    float* C = g_h + (size_t)e * CAP * FF;
    const int* tl = g_tok + e * CAP;

    __shared__ float As[BK][BM];
    __shared__ float Bs[BK][BN];
    int tid = threadIdx.x;
    int n0 = blockIdx.x * BN;
    int rg = tid >> 4, cg = tid & 15;
    int ar = tid >> 2, ac = (tid & 3) << 2;
    int br = tid >> 4, bc = (tid & 15) << 2;

    float acc[8][4];
#pragma unroll
    for (int i = 0; i < 8; i++)
#pragma unroll
        for (int j = 0; j < 4; j++) acc[i][j] = 0.f;

    for (int k0 = 0; k0 < DM; k0 += BK) {
#pragma unroll
        for (int it = 0; it < 2; it++) {
            int r = ar + it * 64;
            int grow = m0 + r;
            float4 av = make_float4(0.f, 0.f, 0.f, 0.f);
            if (grow < M) {
                int trow = tl[grow];
                av = *(const float4*)&X[(size_t)trow * DM + k0 + ac];
            }
            As[ac + 0][r] = av.x;
            As[ac + 1][r] = av.y;
            As[ac + 2][r] = av.z;
            As[ac + 3][r] = av.w;
        }
        float4 bv = *(const float4*)&B[(size_t)(k0 + br) * FF + n0 + bc];
        *(float4*)&Bs[br][bc] = bv;
        __syncthreads();
#pragma unroll
        for (int k = 0; k < BK; k++) {
            float4 a0 = *(const float4*)&As[k][rg * 8];
            float4 a1 = *(const float4*)&As[k][rg * 8 + 4];
            float4 b0 = *(const float4*)&Bs[k][cg * 4];
            float a[8] = {a0.x, a0.y, a0.z, a0.w, a1.x, a1.y, a1.z, a1.w};
            float b[4] = {b0.x, b0.y, b0.z, b0.w};
#pragma unroll
            for (int i = 0; i < 8; i++)
#pragma unroll
                for (int j = 0; j < 4; j++) acc[i][j] += a[i] * b[j];
        }
        __syncthreads();
    }

#pragma unroll
    for (int i = 0; i < 8; i++) {
        int row = m0 + rg * 8 + i;
        if (row >= M) continue;
#pragma unroll
        for (int j = 0; j < 4; j++) {
            int col = n0 + cg * 4 + j;
            float v = acc[i][j] + bias[col];
            v = 0.5f * v * (1.f + erff(v * 0.70710678118654752f));   // exact GELU
            C[(size_t)row * FF + col] = v;
        }
    }
}

// ---------------- MoE grouped GEMM 2: g_h @ W2e + b2e, * gate_weight -> g_eo ----------------
__global__ __launch_bounds__(256) void moe_gemm2_kernel(
    const float* __restrict__ W2, const float* __restrict__ b2)
{
    int e = blockIdx.z;
    int M = g_cnt[e];
    int m0 = blockIdx.y * BM;
    if (m0 >= M) return;
    const float* A = g_h + (size_t)e * CAP * FF;
    const float* B = W2 + (size_t)e * FF * DM;
    const float* bias = b2 + (size_t)e * DM;
    const float* wl = g_wl + e * CAP;
    float* C = g_eo + (size_t)e * CAP * DM;

    __shared__ float As[BK][BM];
    __shared__ float Bs[BK][BN];
    int tid = threadIdx.x;
    int n0 = blockIdx.x * BN;
    int rg = tid >> 4, cg = tid & 15;
    int ar = tid >> 2, ac = (tid & 3) << 2;
    int br = tid >> 4, bc = (tid & 15) << 2;

    float acc[8][4];
#pragma unroll
    for (int i = 0; i < 8; i++)
#pragma unroll
        for (int j = 0; j < 4; j++) acc[i][j] = 0.f;

    for (int k0 = 0; k0 < FF; k0 += BK) {
#pragma unroll
        for (int it = 0; it < 2; it++) {
            int r = ar + it * 64;
            int grow = m0 + r;
            float4 av = make_float4(0.f, 0.f, 0.f, 0.f);
            if (grow < M) av = *(const float4*)&A[(size_t)grow * FF + k0 + ac];
            As[ac + 0][r] = av.x;
            As[ac + 1][r] = av.y;
            As[ac + 2][r] = av.z;
            As[ac + 3][r] = av.w;
        }
        float4 bv = *(const float4*)&B[(size_t)(k0 + br) * DM + n0 + bc];
        *(float4*)&Bs[br][bc] = bv;
        __syncthreads();
#pragma unroll
        for (int k = 0; k < BK; k++) {
            float4 a0 = *(const float4*)&As[k][rg * 8];
            float4 a1 = *(const float4*)&As[k][rg * 8 + 4];
            float4 b0 = *(const float4*)&Bs[k][cg * 4];
            float a[8] = {a0.x, a0.y, a0.z, a0.w, a1.x, a1.y, a1.z, a1.w};
            float b[4] = {b0.x, b0.y, b0.z, b0.w};
#pragma unroll
            for (int i = 0; i < 8; i++)
#pragma unroll
                for (int j = 0; j < 4; j++) acc[i][j] += a[i] * b[j];
        }
        __syncthreads();
    }

#pragma unroll
    for (int i = 0; i < 8; i++) {
        int row = m0 + rg * 8 + i;
        if (row >= M) continue;
        float w = wl[row];
#pragma unroll
        for (int j = 0; j < 4; j++) {
            int col = n0 + cg * 4 + j;
            C[(size_t)row * DM + col] = (acc[i][j] + bias[col]) * w;
        }
    }
}

// ---------------- fused sliding-window attention ----------------
#define APAD 68
__global__ __launch_bounds__(256) void attn_kernel(float* __restrict__ out)
{
    __shared__ float Qs[64][APAD];
    __shared__ float Ks[32][APAD];
    __shared__ float Vs[32][APAD];
    __shared__ float Ss[64][33];
    __shared__ float mS[64], lS[64], cS[64];

    int h = blockIdx.y;
    int q0 = blockIdx.x * 64;
    int tid = threadIdx.x;
    int q = tid & 63;
    int kg = tid >> 6;   // score phase key group
    int dp = tid >> 6;   // pv phase dim group

    const float* qhead = g_q + (size_t)h * SEQ * DH;
    const float* khead = g_k + (size_t)h * SEQ * DH;
    const float* vhead = g_v + (size_t)h * SEQ * DH;

#pragma unroll
    for (int i = 0; i < 4; i++) {
        int idx = tid + i * 256;
        int r = idx >> 4;
        int c = (idx & 15) << 2;
        float4 v = *(const float4*)&qhead[(size_t)(q0 + r) * DH + c];
        *(float4*)&Qs[r][c] = v;
    }
    if (tid < 64) { mS[tid] = -1e9f; lS[tid] = 0.f; }

    float acc[16];
#pragma unroll
    for (int i = 0; i < 16; i++) acc[i] = 0.f;
    __syncthreads();

    for (int kt = 0; kt < 18; kt++) {
        int kbase = q0 - 256 + kt * 32;
        if (kbase + 31 < 0 || kbase >= SEQ) continue;

#pragma unroll
        for (int i = 0; i < 2; i++) {
            int idx = tid + i * 256;
            int r = idx >> 4;
            int c = (idx & 15) << 2;
            int kpos = kbase + r;
            float4 kv = make_float4(0.f, 0.f, 0.f, 0.f);
            float4 vv = kv;
            if (kpos >= 0 && kpos < SEQ) {
                kv = *(const float4*)&khead[(size_t)kpos * DH + c];
                vv = *(const float4*)&vhead[(size_t)kpos * DH + c];
            }
            *(float4*)&Ks[r][c] = kv;
            *(float4*)&Vs[r][c] = vv;
        }
        __syncthreads();

        // scores: 8 per thread
        float s[8];
#pragma unroll
        for (int j = 0; j < 8; j++) s[j] = 0.f;
#pragma unroll
        for (int d = 0; d < 64; d += 4) {
            float4 q4 = *(const float4*)&Qs[q][d];
#pragma unroll
            for (int j = 0; j < 8; j++) {
                float4 k4 = *(const float4*)&Ks[kg * 8 + j][d];
                s[j] += q4.x * k4.x + q4.y * k4.y + q4.z * k4.z + q4.w * k4.w;
            }
        }
        int qpos = q0 + q;
#pragma unroll
        for (int j = 0; j < 8; j++) {
            int kpos = kbase + kg * 8 + j;
            bool valid = (kpos >= 0) && (kpos < SEQ) &&
                         (kpos >= qpos - WIN) && (kpos <= qpos + WIN);
            Ss[q][kg * 8 + j] = valid ? s[j] : -1e9f;
        }
        __syncthreads();

        // row softmax stats
        if (tid < 64) {
            int r = tid;
            float mold = mS[r];
            float tmax = -1e9f;
#pragma unroll
            for (int kk = 0; kk < 32; kk++) tmax = fmaxf(tmax, Ss[r][kk]);
            float mnew = fmaxf(mold, tmax);
            float corr = __expf(mold - mnew);
            float sum = 0.f;
#pragma unroll
            for (int kk = 0; kk < 32; kk++) {
                float p = __expf(Ss[r][kk] - mnew);
                Ss[r][kk] = p;
                sum += p;
            }
            lS[r] = lS[r] * corr + sum;
            mS[r] = mnew;
            cS[r] = corr;
        }
        __syncthreads();

        // accumulate P@V
        float corr = cS[q];
#pragma unroll
        for (int i = 0; i < 16; i++) acc[i] *= corr;
#pragma unroll
        for (int kk = 0; kk < 32; kk++) {
            float p = Ss[q][kk];
#pragma unroll
            for (int i4 = 0; i4 < 4; i4++) {
                float4 v4 = *(const float4*)&Vs[kk][dp * 16 + i4 * 4];
                acc[i4 * 4 + 0] += p * v4.x;
                acc[i4 * 4 + 1] += p * v4.y;
                acc[i4 * 4 + 2] += p * v4.z;
                acc[i4 * 4 + 3] += p * v4.w;
            }
        }
        __syncthreads();
    }

    float inv = 1.f / lS[q];
    float* o = out + (size_t)(q0 + q) * DM + h * DH + dp * 16;
#pragma unroll
    for (int i4 = 0; i4 < 4; i4++) {
        float4 v;
        v.x = acc[i4 * 4 + 0] * inv;
        v.y = acc[i4 * 4 + 1] * inv;
        v.z = acc[i4 * 4 + 2] * inv;
        v.w = acc[i4 * 4 + 3] * inv;
        *(float4*)&o[i4 * 4] = v;
    }
}

// ---------------- layer norm (row-wise) ----------------
__global__ __launch_bounds__(256) void ln_kernel(
    const float* __restrict__ in, const float* __restrict__ g,
    const float* __restrict__ b, float* __restrict__ out)
{
    __shared__ float rs[8], rs2[8];
    int row = blockIdx.x;
    int tid = threadIdx.x;
    const float* x = in + (size_t)row * DM;
    float vals[3];
    float s = 0.f, s2 = 0.f;
#pragma unroll
    for (int i = 0; i < 3; i++) {
        float v = x[tid + i * 256];
        vals[i] = v;
        s += v;
        s2 += v * v;
    }
    int lane = tid & 31, w = tid >> 5;
#pragma unroll
    for (int o = 16; o; o >>= 1) {
        s += __shfl_down_sync(0xffffffffu, s, o);
        s2 += __shfl_down_sync(0xffffffffu, s2, o);
    }
    if (lane == 0) { rs[w] = s; rs2[w] = s2; }
    __syncthreads();
    if (tid == 0) {
        float a = 0.f, c = 0.f;
#pragma unroll
        for (int i = 0; i < 8; i++) { a += rs[i]; c += rs2[i]; }
        rs[0] = a;
        rs2[0] = c;
    }
    __syncthreads();
    float mean = rs[0] * (1.f / DM);
    float var = rs2[0] * (1.f / DM) - mean * mean;
    float rstd = rsqrtf(var + 1e-5f);
    float* o = out + (size_t)row * DM;
#pragma unroll
    for (int i = 0; i < 3; i++) {
        int col = tid + i * 256;
        o[col] = (vals[i] - mean) * rstd * g[col] + b[col];
    }
}

// ---------------- gating: logits, top-2, softmax, expert lists ----------------
__global__ __launch_bounds__(256) void gating_kernel(
    const float* __restrict__ x1, const float* __restrict__ gW,
    const float* __restrict__ gb, float* __restrict__ gate_out)
{
    __shared__ float xs[DM];
    __shared__ float lg[8];
    int row = blockIdx.x;
    int tid = threadIdx.x;
    for (int i = tid; i < DM; i += 256) xs[i] = x1[(size_t)row * DM + i];
    __syncthreads();
    int w = tid >> 5, lane = tid & 31;
    if (w < NE) {
        float p = 0.f;
        for (int d = lane; d < DM; d += 32) p += xs[d] * gW[d * NE + w];
#pragma unroll
        for (int o = 16; o; o >>= 1) p += __shfl_down_sync(0xffffffffu, p, o);
        if (lane == 0) lg[w] = p + gb[w];
    }
    __syncthreads();
    if (tid == 0) {
        int e1 = 0;
        float v1 = lg[0];
        for (int e = 1; e < NE; e++)
            if (lg[e] > v1) { v1 = lg[e]; e1 = e; }
        int e2 = -1;
        float v2 = -1e30f;
        for (int e = 0; e < NE; e++) {
            if (e == e1) continue;
            if (lg[e] > v2) { v2 = lg[e]; e2 = e; }
        }
        float z = expf(v2 - v1);
        float w1 = 1.f / (1.f + z);
        float w2 = z / (1.f + z);
        float* go = gate_out + (size_t)row * NE;
#pragma unroll
        for (int e = 0; e < NE; e++) go[e] = 0.f;
        go[e1] = w1;
        go[e2] = w2;
        int s1 = atomicAdd(&g_cnt[e1], 1);
        g_tok[e1 * CAP + s1] = row;
        g_wl[e1 * CAP + s1] = w1;
        g_pos[row * 2 + 0] = e1 * CAP + s1;
        int s2 = atomicAdd(&g_cnt[e2], 1);
        g_tok[e2 * CAP + s2] = row;
        g_wl[e2 * CAP + s2] = w2;
        g_pos[row * 2 + 1] = e2 * CAP + s2;
    }
}

// ---------------- combine two expert outputs per token ----------------
__global__ __launch_bounds__(192) void combine_kernel()
{
    int t = blockIdx.x;
    int p0 = g_pos[t * 2 + 0];
    int p1 = g_pos[t * 2 + 1];
    const float* a = g_eo + (size_t)p0 * DM;
    const float* b = g_eo + (size_t)p1 * DM;
    float* o = g_moe + (size_t)t * DM;
    int i = threadIdx.x * 4;
    float4 av = *(const float4*)&a[i];
    float4 bv = *(const float4*)&b[i];
    float4 v;
    v.x = av.x + bv.x;
    v.y = av.y + bv.y;
    v.z = av.z + bv.z;
    v.w = av.w + bv.w;
    *(float4*)&o[i] = v;
}

// ---------------- launch ----------------
extern "C" void kernel_launch(void* const* d_in, const int* in_sizes, int n_in,
                              void* d_out, int out_size)
{
    (void)in_sizes; (void)n_in; (void)out_size;
    const float* x     = (const float*)d_in[0];
    const float* Wq    = (const float*)d_in[1];
    const float* bq    = (const float*)d_in[2];
    const float* Wk    = (const float*)d_in[3];
    const float* bk    = (const float*)d_in[4];
    const float* Wv    = (const float*)d_in[5];
    const float* bv    = (const float*)d_in[6];
    const float* Wo    = (const float*)d_in[7];
    const float* bo    = (const float*)d_in[8];
    const float* ln1g  = (const float*)d_in[9];
    const float* ln1b  = (const float*)d_in[10];
    const float* gateW = (const float*)d_in[11];
    const float* gateb = (const float*)d_in[12];
    const float* W1e   = (const float*)d_in[13];
    const float* b1e   = (const float*)d_in[14];
    const float* W2e   = (const float*)d_in[15];
    const float* b2e   = (const float*)d_in[16];
    const float* Wd    = (const float*)d_in[17];
    const float* bd    = (const float*)d_in[18];
    const float* ln2g  = (const float*)d_in[19];
    const float* ln2b  = (const float*)d_in[20];

    float* out = (float*)d_out;
    float* gate_out = out + (size_t)SEQ * DM;

    float *pq, *pk, *pv, *pattno, *ptmp, *px1, *pmoe;
    cudaGetSymbolAddress((void**)&pq, g_q);
    cudaGetSymbolAddress((void**)&pk, g_k);
    cudaGetSymbolAddress((void**)&pv, g_v);
    cudaGetSymbolAddress((void**)&pattno, g_attno);
    cudaGetSymbolAddress((void**)&ptmp, g_tmp);
    cudaGetSymbolAddress((void**)&px1, g_x1);
    cudaGetSymbolAddress((void**)&pmoe, g_moe);

    dim3 gemm_grid(DM / BN, SEQ / BM);   // (12, 32)

    reset_kernel<<<1, 32>>>();

    // QKV projections (head-scattered layout; q pre-scaled by 1/sqrt(64))
    gemm_kernel<<<gemm_grid, 256>>>(x, Wq, bq, pq, SEQ, DM, DM, nullptr, 0.125f, 1);
    gemm_kernel<<<gemm_grid, 256>>>(x, Wk, bk, pk, SEQ, DM, DM, nullptr, 1.0f, 1);
    gemm_kernel<<<gemm_grid, 256>>>(x, Wv, bv, pv, SEQ, DM, DM, nullptr, 1.0f, 1);

    // sliding-window attention
    attn_kernel<<<dim3(SEQ / 64, NH), 256>>>(pattno);

    // Wo projection + residual(hidden) -> LN1 -> x1
    gemm_kernel<<<gemm_grid, 256>>>(pattno, Wo, bo, ptmp, SEQ, DM, DM, x, 1.0f, 2);
    ln_kernel<<<SEQ, 256>>>(ptmp, ln1g, ln1b, px1);

    // gating (writes gate_weights output + expert lists)
    gating_kernel<<<SEQ, 256>>>(px1, gateW, gateb, gate_out);

    // MoE expert FFN (grouped, sparse top-2)
    moe_gemm1_kernel<<<dim3(FF / BN, SEQ / BM, NE), 256>>>(px1, W1e, b1e);
    moe_gemm2_kernel<<<dim3(DM / BN, SEQ / BM, NE), 256>>>(W2e, b2e);
    combine_kernel<<<SEQ, 192>>>();

    // Wd projection + residual(x1) -> LN2 -> layer_output
    gemm_kernel<<<gemm_grid, 256>>>(pmoe, Wd, bd, ptmp, SEQ, DM, DM, px1, 1.0f, 2);
    ln_kernel<<<SEQ, 256>>>(ptmp, ln2g, ln2b, out);
}

// round 4
// speedup vs baseline: 1.5837x; 1.5837x over previous
#include <cuda_runtime.h>
#include <math.h>

#define SEQ 4096
#define DM  768
#define NH  12
#define DH  64
#define FF  3072
#define NE  7
#define WIN 256
#define CAP 4096

// ---------------- scratch (static device globals; no allocation) ----------------
__device__ float g_q[NH * SEQ * DH];
__device__ float g_k[NH * SEQ * DH];
__device__ float g_v[NH * SEQ * DH];
__device__ float g_attno[SEQ * DM];
__device__ float g_tmp[SEQ * DM];
__device__ float g_x1[SEQ * DM];
__device__ float g_moe[SEQ * DM];
__device__ float g_h[NE * CAP * FF];     // 352 MB
__device__ float g_eo[NE * CAP * DM];    // 88 MB
__device__ int   g_cnt[NE];
__device__ int   g_tok[NE * CAP];
__device__ float g_wl[NE * CAP];
__device__ int   g_pos[SEQ * 2];

// ---------------- reset ----------------
__global__ void reset_kernel() {
    if (threadIdx.x < NE) g_cnt[threadIdx.x] = 0;
}

// ======================================================================
// fp32 SIMT GEMM (kept for the gating-critical path: QKV, Wo)
// ======================================================================
#define BM 128
#define BN 64
#define BK 16

__global__ __launch_bounds__(256) void gemm_kernel(
    const float* __restrict__ A, const float* __restrict__ B,
    const float* __restrict__ bias, float* __restrict__ C,
    int M, int N, int K, const float* __restrict__ residual,
    float scale, int mode)
{
    __shared__ float As[BK][BM];
    __shared__ float Bs[BK][BN];
    int tid = threadIdx.x;
    int m0 = blockIdx.y * BM;
    int n0 = blockIdx.x * BN;
    int rg = tid >> 4;
    int cg = tid & 15;
    int ar = tid >> 2;
    int ac = (tid & 3) << 2;
    int br = tid >> 4;
    int bc = (tid & 15) << 2;

    float acc[8][4];
#pragma unroll
    for (int i = 0; i < 8; i++)
#pragma unroll
        for (int j = 0; j < 4; j++) acc[i][j] = 0.f;

    for (int k0 = 0; k0 < K; k0 += BK) {
#pragma unroll
        for (int it = 0; it < 2; it++) {
            int r = ar + it * 64;
            float4 av = *(const float4*)&A[(size_t)(m0 + r) * K + k0 + ac];
            As[ac + 0][r] = av.x;
            As[ac + 1][r] = av.y;
            As[ac + 2][r] = av.z;
            As[ac + 3][r] = av.w;
        }
        float4 bv = *(const float4*)&B[(size_t)(k0 + br) * N + n0 + bc];
        *(float4*)&Bs[br][bc] = bv;
        __syncthreads();
#pragma unroll
        for (int k = 0; k < BK; k++) {
            float4 a0 = *(const float4*)&As[k][rg * 8];
            float4 a1 = *(const float4*)&As[k][rg * 8 + 4];
            float4 b0 = *(const float4*)&Bs[k][cg * 4];
            float a[8] = {a0.x, a0.y, a0.z, a0.w, a1.x, a1.y, a1.z, a1.w};
            float b[4] = {b0.x, b0.y, b0.z, b0.w};
#pragma unroll
            for (int i = 0; i < 8; i++)
#pragma unroll
                for (int j = 0; j < 4; j++) acc[i][j] += a[i] * b[j];
        }
        __syncthreads();
    }

#pragma unroll
    for (int i = 0; i < 8; i++) {
        int row = m0 + rg * 8 + i;
#pragma unroll
        for (int j = 0; j < 4; j++) {
            int col = n0 + cg * 4 + j;
            float v = acc[i][j] + bias[col];
            if (mode == 0) {
                C[(size_t)row * N + col] = v;
            } else if (mode == 1) {
                C[((size_t)(col >> 6) * M + row) * 64 + (col & 63)] = v * scale;
            } else {
                C[(size_t)row * N + col] = v + residual[(size_t)row * N + col];
            }
        }
    }
}

// ======================================================================
// tf32 tensor-core GEMM machinery (mma.sync.m16n8k8)
// BM=128, BN=64, BK=16, 256 threads = 8 warps in 4x2, warp tile 32x32.
// ======================================================================
#define APADM 136   // BM + 8 : conflict-free fragment loads
#define APADN 72    // BN + 8

__device__ __forceinline__ unsigned f2tf(float f) {
    unsigned u;
    asm("cvt.rna.tf32.f32 %0, %1;" : "=r"(u) : "f"(f));
    return u;
}

__device__ __forceinline__ void mma_tf32(float* c, const unsigned* a, const unsigned* b) {
    asm volatile(
        "mma.sync.aligned.m16n8k8.row.col.f32.tf32.tf32.f32 "
        "{%0,%1,%2,%3}, {%4,%5,%6,%7}, {%8,%9}, {%0,%1,%2,%3};"
        : "+f"(c[0]), "+f"(c[1]), "+f"(c[2]), "+f"(c[3])
        : "r"(a[0]), "r"(a[1]), "r"(a[2]), "r"(a[3]),
          "r"(b[0]), "r"(b[1]));
}

// shared mainloop body: fills acc[2][4][4] for this block/warp
// A_loader: lambda-free — implemented via macro parameters in each kernel
#define MMA_DECLS()                                                        \
    __shared__ unsigned As[BK][APADM];                                     \
    __shared__ unsigned Bs[BK][APADN];                                     \
    int tid = threadIdx.x;                                                 \
    int ar = tid >> 2, ac = (tid & 3) << 2;                                \
    int br = tid >> 4, bc = (tid & 15) << 2;                               \
    int w = tid >> 5, lane = tid & 31;                                     \
    int m0w = (w >> 1) * 32, n0w = (w & 1) * 32;                           \
    int g = lane >> 2, t = lane & 3;                                       \
    float acc[2][4][4];                                                    \
    _Pragma("unroll")                                                      \
    for (int mi = 0; mi < 2; mi++)                                         \
        _Pragma("unroll")                                                  \
        for (int ni = 0; ni < 4; ni++)                                     \
            _Pragma("unroll")                                              \
            for (int j = 0; j < 4; j++) acc[mi][ni][j] = 0.f;

#define MMA_COMPUTE()                                                      \
    __syncthreads();                                                       \
    _Pragma("unroll")                                                      \
    for (int kk = 0; kk < BK; kk += 8) {                                   \
        unsigned afr[2][4], bfr[4][2];                                     \
        _Pragma("unroll")                                                  \
        for (int mi = 0; mi < 2; mi++) {                                   \
            int mb = m0w + mi * 16 + g;                                    \
            afr[mi][0] = As[kk + t][mb];                                   \
            afr[mi][1] = As[kk + t][mb + 8];                               \
            afr[mi][2] = As[kk + t + 4][mb];                               \
            afr[mi][3] = As[kk + t + 4][mb + 8];                           \
        }                                                                  \
        _Pragma("unroll")                                                  \
        for (int ni = 0; ni < 4; ni++) {                                   \
            int nb = n0w + ni * 8 + g;                                     \
            bfr[ni][0] = Bs[kk + t][nb];                                   \
            bfr[ni][1] = Bs[kk + t + 4][nb];                               \
        }                                                                  \
        _Pragma("unroll")                                                  \
        for (int mi = 0; mi < 2; mi++)                                     \
            _Pragma("unroll")                                              \
            for (int ni = 0; ni < 4; ni++)                                 \
                mma_tf32(acc[mi][ni], afr[mi], bfr[ni]);                   \
    }                                                                      \
    __syncthreads();

// ---------------- MoE GEMM 1 (tf32): gather + GELU ----------------
__global__ __launch_bounds__(256) void mma_moe_gemm1(
    const float* __restrict__ X, const float* __restrict__ W1,
    const float* __restrict__ b1)
{
    int e = blockIdx.z;
    int M = g_cnt[e];
    int m0 = blockIdx.y * BM;
    if (m0 >= M) return;
    const float* B = W1 + (size_t)e * DM * FF;
    const float* bias = b1 + (size_t)e * FF;
    float* C = g_h + (size_t)e * CAP * FF;
    const int* tl = g_tok + e * CAP;
    int n0 = blockIdx.x * BN;

    MMA_DECLS();

    for (int k0 = 0; k0 < DM; k0 += BK) {
#pragma unroll
        for (int it = 0; it < 2; it++) {
            int r = ar + it * 64;
            int grow = m0 + r;
            float4 av = make_float4(0.f, 0.f, 0.f, 0.f);
            if (grow < M) {
                int trow = tl[grow];
                av = *(const float4*)&X[(size_t)trow * DM + k0 + ac];
            }
            As[ac + 0][r] = f2tf(av.x);
            As[ac + 1][r] = f2tf(av.y);
            As[ac + 2][r] = f2tf(av.z);
            As[ac + 3][r] = f2tf(av.w);
        }
        {
            float4 bv = *(const float4*)&B[(size_t)(k0 + br) * FF + n0 + bc];
            Bs[br][bc + 0] = f2tf(bv.x);
            Bs[br][bc + 1] = f2tf(bv.y);
            Bs[br][bc + 2] = f2tf(bv.z);
            Bs[br][bc + 3] = f2tf(bv.w);
        }
        MMA_COMPUTE();
    }

#pragma unroll
    for (int mi = 0; mi < 2; mi++) {
#pragma unroll
        for (int ni = 0; ni < 4; ni++) {
            int col = n0 + n0w + ni * 8 + 2 * t;
            float bv0 = bias[col], bv1 = bias[col + 1];
#pragma unroll
            for (int half = 0; half < 2; half++) {
                int row = m0 + m0w + mi * 16 + g + half * 8;
                if (row >= M) continue;
                float v0 = acc[mi][ni][half * 2 + 0] + bv0;
                float v1 = acc[mi][ni][half * 2 + 1] + bv1;
                v0 = 0.5f * v0 * (1.f + erff(v0 * 0.70710678118654752f));
                v1 = 0.5f * v1 * (1.f + erff(v1 * 0.70710678118654752f));
                C[(size_t)row * FF + col]     = v0;
                C[(size_t)row * FF + col + 1] = v1;
            }
        }
    }
}

// ---------------- MoE GEMM 2 (tf32): * gate weight ----------------
__global__ __launch_bounds__(256) void mma_moe_gemm2(
    const float* __restrict__ W2, const float* __restrict__ b2)
{
    int e = blockIdx.z;
    int M = g_cnt[e];
    int m0 = blockIdx.y * BM;
    if (m0 >= M) return;
    const float* A = g_h + (size_t)e * CAP * FF;
    const float* B = W2 + (size_t)e * FF * DM;
    const float* bias = b2 + (size_t)e * DM;
    const float* wl = g_wl + e * CAP;
    float* C = g_eo + (size_t)e * CAP * DM;
    int n0 = blockIdx.x * BN;

    MMA_DECLS();

    for (int k0 = 0; k0 < FF; k0 += BK) {
#pragma unroll
        for (int it = 0; it < 2; it++) {
            int r = ar + it * 64;
            int grow = m0 + r;
            float4 av = make_float4(0.f, 0.f, 0.f, 0.f);
            if (grow < M) av = *(const float4*)&A[(size_t)grow * FF + k0 + ac];
            As[ac + 0][r] = f2tf(av.x);
            As[ac + 1][r] = f2tf(av.y);
            As[ac + 2][r] = f2tf(av.z);
            As[ac + 3][r] = f2tf(av.w);
        }
        {
            float4 bv = *(const float4*)&B[(size_t)(k0 + br) * DM + n0 + bc];
            Bs[br][bc + 0] = f2tf(bv.x);
            Bs[br][bc + 1] = f2tf(bv.y);
            Bs[br][bc + 2] = f2tf(bv.z);
            Bs[br][bc + 3] = f2tf(bv.w);
        }
        MMA_COMPUTE();
    }

#pragma unroll
    for (int mi = 0; mi < 2; mi++) {
#pragma unroll
        for (int ni = 0; ni < 4; ni++) {
            int col = n0 + n0w + ni * 8 + 2 * t;
            float bv0 = bias[col], bv1 = bias[col + 1];
#pragma unroll
            for (int half = 0; half < 2; half++) {
                int row = m0 + m0w + mi * 16 + g + half * 8;
                if (row >= M) continue;
                float wv = wl[row];
                C[(size_t)row * DM + col]     = (acc[mi][ni][half * 2 + 0] + bv0) * wv;
                C[(size_t)row * DM + col + 1] = (acc[mi][ni][half * 2 + 1] + bv1) * wv;
            }
        }
    }
}

// ---------------- Wd GEMM (tf32): + bias + residual ----------------
__global__ __launch_bounds__(256) void mma_gemm_res(
    const float* __restrict__ A, const float* __restrict__ B,
    const float* __restrict__ bias, float* __restrict__ C,
    const float* __restrict__ R, int M, int N, int K)
{
    int m0 = blockIdx.y * BM;
    int n0 = blockIdx.x * BN;

    MMA_DECLS();

    for (int k0 = 0; k0 < K; k0 += BK) {
#pragma unroll
        for (int it = 0; it < 2; it++) {
            int r = ar + it * 64;
            float4 av = *(const float4*)&A[(size_t)(m0 + r) * K + k0 + ac];
            As[ac + 0][r] = f2tf(av.x);
            As[ac + 1][r] = f2tf(av.y);
            As[ac + 2][r] = f2tf(av.z);
            As[ac + 3][r] = f2tf(av.w);
        }
        {
            float4 bv = *(const float4*)&B[(size_t)(k0 + br) * N + n0 + bc];
            Bs[br][bc + 0] = f2tf(bv.x);
            Bs[br][bc + 1] = f2tf(bv.y);
            Bs[br][bc + 2] = f2tf(bv.z);
            Bs[br][bc + 3] = f2tf(bv.w);
        }
        MMA_COMPUTE();
    }

#pragma unroll
    for (int mi = 0; mi < 2; mi++) {
#pragma unroll
        for (int ni = 0; ni < 4; ni++) {
            int col = n0 + n0w + ni * 8 + 2 * t;
            float bv0 = bias[col], bv1 = bias[col + 1];
#pragma unroll
            for (int half = 0; half < 2; half++) {
                int row = m0 + m0w + mi * 16 + g + half * 8;
                size_t idx = (size_t)row * N + col;
                C[idx]     = acc[mi][ni][half * 2 + 0] + bv0 + R[idx];
                C[idx + 1] = acc[mi][ni][half * 2 + 1] + bv1 + R[idx + 1];
            }
        }
    }
}

// ---------------- fused sliding-window attention ----------------
#define APAD 68
__global__ __launch_bounds__(256) void attn_kernel(float* __restrict__ out)
{
    __shared__ float Qs[64][APAD];
    __shared__ float Ks[32][APAD];
    __shared__ float Vs[32][APAD];
    __shared__ float Ss[64][33];
    __shared__ float mS[64], lS[64], cS[64];

    int h = blockIdx.y;
    int q0 = blockIdx.x * 64;
    int tid = threadIdx.x;
    int q = tid & 63;
    int kg = tid >> 6;
    int dp = tid >> 6;

    const float* qhead = g_q + (size_t)h * SEQ * DH;
    const float* khead = g_k + (size_t)h * SEQ * DH;
    const float* vhead = g_v + (size_t)h * SEQ * DH;

#pragma unroll
    for (int i = 0; i < 4; i++) {
        int idx = tid + i * 256;
        int r = idx >> 4;
        int c = (idx & 15) << 2;
        float4 v = *(const float4*)&qhead[(size_t)(q0 + r) * DH + c];
        *(float4*)&Qs[r][c] = v;
    }
    if (tid < 64) { mS[tid] = -1e9f; lS[tid] = 0.f; }

    float acc[16];
#pragma unroll
    for (int i = 0; i < 16; i++) acc[i] = 0.f;
    __syncthreads();

    for (int kt = 0; kt < 18; kt++) {
        int kbase = q0 - 256 + kt * 32;
        if (kbase + 31 < 0 || kbase >= SEQ) continue;

#pragma unroll
        for (int i = 0; i < 2; i++) {
            int idx = tid + i * 256;
            int r = idx >> 4;
            int c = (idx & 15) << 2;
            int kpos = kbase + r;
            float4 kv = make_float4(0.f, 0.f, 0.f, 0.f);
            float4 vv = kv;
            if (kpos >= 0 && kpos < SEQ) {
                kv = *(const float4*)&khead[(size_t)kpos * DH + c];
                vv = *(const float4*)&vhead[(size_t)kpos * DH + c];
            }
            *(float4*)&Ks[r][c] = kv;
            *(float4*)&Vs[r][c] = vv;
        }
        __syncthreads();

        float s[8];
#pragma unroll
        for (int j = 0; j < 8; j++) s[j] = 0.f;
#pragma unroll
        for (int d = 0; d < 64; d += 4) {
            float4 q4 = *(const float4*)&Qs[q][d];
#pragma unroll
            for (int j = 0; j < 8; j++) {
                float4 k4 = *(const float4*)&Ks[kg * 8 + j][d];
                s[j] += q4.x * k4.x + q4.y * k4.y + q4.z * k4.z + q4.w * k4.w;
            }
        }
        int qpos = q0 + q;
#pragma unroll
        for (int j = 0; j < 8; j++) {
            int kpos = kbase + kg * 8 + j;
            bool valid = (kpos >= 0) && (kpos < SEQ) &&
                         (kpos >= qpos - WIN) && (kpos <= qpos + WIN);
            Ss[q][kg * 8 + j] = valid ? s[j] : -1e9f;
        }
        __syncthreads();

        if (tid < 64) {
            int r = tid;
            float mold = mS[r];
            float tmax = -1e9f;
#pragma unroll
            for (int kk = 0; kk < 32; kk++) tmax = fmaxf(tmax, Ss[r][kk]);
            float mnew = fmaxf(mold, tmax);
            float corr = __expf(mold - mnew);
            float sum = 0.f;
#pragma unroll
            for (int kk = 0; kk < 32; kk++) {
                float p = __expf(Ss[r][kk] - mnew);
                Ss[r][kk] = p;
                sum += p;
            }
            lS[r] = lS[r] * corr + sum;
            mS[r] = mnew;
            cS[r] = corr;
        }
        __syncthreads();

        float corr = cS[q];
#pragma unroll
        for (int i = 0; i < 16; i++) acc[i] *= corr;
#pragma unroll
        for (int kk = 0; kk < 32; kk++) {
            float p = Ss[q][kk];
#pragma unroll
            for (int i4 = 0; i4 < 4; i4++) {
                float4 v4 = *(const float4*)&Vs[kk][dp * 16 + i4 * 4];
                acc[i4 * 4 + 0] += p * v4.x;
                acc[i4 * 4 + 1] += p * v4.y;
                acc[i4 * 4 + 2] += p * v4.z;
                acc[i4 * 4 + 3] += p * v4.w;
            }
        }
        __syncthreads();
    }

    float inv = 1.f / lS[q];
    float* o = out + (size_t)(q0 + q) * DM + h * DH + dp * 16;
#pragma unroll
    for (int i4 = 0; i4 < 4; i4++) {
        float4 v;
        v.x = acc[i4 * 4 + 0] * inv;
        v.y = acc[i4 * 4 + 1] * inv;
        v.z = acc[i4 * 4 + 2] * inv;
        v.w = acc[i4 * 4 + 3] * inv;
        *(float4*)&o[i4 * 4] = v;
    }
}

// ---------------- layer norm (row-wise) ----------------
__global__ __launch_bounds__(256) void ln_kernel(
    const float* __restrict__ in, const float* __restrict__ g,
    const float* __restrict__ b, float* __restrict__ out)
{
    __shared__ float rs[8], rs2[8];
    int row = blockIdx.x;
    int tid = threadIdx.x;
    const float* x = in + (size_t)row * DM;
    float vals[3];
    float s = 0.f, s2 = 0.f;
#pragma unroll
    for (int i = 0; i < 3; i++) {
        float v = x[tid + i * 256];
        vals[i] = v;
        s += v;
        s2 += v * v;
    }
    int lane = tid & 31, w = tid >> 5;
#pragma unroll
    for (int o = 16; o; o >>= 1) {
        s += __shfl_down_sync(0xffffffffu, s, o);
        s2 += __shfl_down_sync(0xffffffffu, s2, o);
    }
    if (lane == 0) { rs[w] = s; rs2[w] = s2; }
    __syncthreads();
    if (tid == 0) {
        float a = 0.f, c = 0.f;
#pragma unroll
        for (int i = 0; i < 8; i++) { a += rs[i]; c += rs2[i]; }
        rs[0] = a;
        rs2[0] = c;
    }
    __syncthreads();
    float mean = rs[0] * (1.f / DM);
    float var = rs2[0] * (1.f / DM) - mean * mean;
    float rstd = rsqrtf(var + 1e-5f);
    float* o = out + (size_t)row * DM;
#pragma unroll
    for (int i = 0; i < 3; i++) {
        int col = tid + i * 256;
        o[col] = (vals[i] - mean) * rstd * g[col] + b[col];
    }
}

// ---------------- gating: logits, top-2, softmax, expert lists ----------------
__global__ __launch_bounds__(256) void gating_kernel(
    const float* __restrict__ x1, const float* __restrict__ gW,
    const float* __restrict__ gb, float* __restrict__ gate_out)
{
    __shared__ float xs[DM];
    __shared__ float lg[8];
    int row = blockIdx.x;
    int tid = threadIdx.x;
    for (int i = tid; i < DM; i += 256) xs[i] = x1[(size_t)row * DM + i];
    __syncthreads();
    int w = tid >> 5, lane = tid & 31;
    if (w < NE) {
        float p = 0.f;
        for (int d = lane; d < DM; d += 32) p += xs[d] * gW[d * NE + w];
#pragma unroll
        for (int o = 16; o; o >>= 1) p += __shfl_down_sync(0xffffffffu, p, o);
        if (lane == 0) lg[w] = p + gb[w];
    }
    __syncthreads();
    if (tid == 0) {
        int e1 = 0;
        float v1 = lg[0];
        for (int e = 1; e < NE; e++)
            if (lg[e] > v1) { v1 = lg[e]; e1 = e; }
        int e2 = -1;
        float v2 = -1e30f;
        for (int e = 0; e < NE; e++) {
            if (e == e1) continue;
            if (lg[e] > v2) { v2 = lg[e]; e2 = e; }
        }
        float z = expf(v2 - v1);
        float w1 = 1.f / (1.f + z);
        float w2 = z / (1.f + z);
        float* go = gate_out + (size_t)row * NE;
#pragma unroll
        for (int e = 0; e < NE; e++) go[e] = 0.f;
        go[e1] = w1;
        go[e2] = w2;
        int s1 = atomicAdd(&g_cnt[e1], 1);
        g_tok[e1 * CAP + s1] = row;
        g_wl[e1 * CAP + s1] = w1;
        g_pos[row * 2 + 0] = e1 * CAP + s1;
        int s2 = atomicAdd(&g_cnt[e2], 1);
        g_tok[e2 * CAP + s2] = row;
        g_wl[e2 * CAP + s2] = w2;
        g_pos[row * 2 + 1] = e2 * CAP + s2;
    }
}

// ---------------- combine two expert outputs per token ----------------
__global__ __launch_bounds__(192) void combine_kernel()
{
    int t = blockIdx.x;
    int p0 = g_pos[t * 2 + 0];
    int p1 = g_pos[t * 2 + 1];
    const float* a = g_eo + (size_t)p0 * DM;
    const float* b = g_eo + (size_t)p1 * DM;
    float* o = g_moe + (size_t)t * DM;
    int i = threadIdx.x * 4;
    float4 av = *(const float4*)&a[i];
    float4 bv = *(const float4*)&b[i];
    float4 v;
    v.x = av.x + bv.x;
    v.y = av.y + bv.y;
    v.z = av.z + bv.z;
    v.w = av.w + bv.w;
    *(float4*)&o[i] = v;
}

// ---------------- launch ----------------
extern "C" void kernel_launch(void* const* d_in, const int* in_sizes, int n_in,
                              void* d_out, int out_size)
{
    (void)in_sizes; (void)n_in; (void)out_size;
    const float* x     = (const float*)d_in[0];
    const float* Wq    = (const float*)d_in[1];
    const float* bq    = (const float*)d_in[2];
    const float* Wk    = (const float*)d_in[3];
    const float* bk    = (const float*)d_in[4];
    const float* Wv    = (const float*)d_in[5];
    const float* bv    = (const float*)d_in[6];
    const float* Wo    = (const float*)d_in[7];
    const float* bo    = (const float*)d_in[8];
    const float* ln1g  = (const float*)d_in[9];
    const float* ln1b  = (const float*)d_in[10];
    const float* gateW = (const float*)d_in[11];
    const float* gateb = (const float*)d_in[12];
    const float* W1e   = (const float*)d_in[13];
    const float* b1e   = (const float*)d_in[14];
    const float* W2e   = (const float*)d_in[15];
    const float* b2e   = (const float*)d_in[16];
    const float* Wd    = (const float*)d_in[17];
    const float* bd    = (const float*)d_in[18];
    const float* ln2g  = (const float*)d_in[19];
    const float* ln2b  = (const float*)d_in[20];

    float* out = (float*)d_out;
    float* gate_out = out + (size_t)SEQ * DM;

    float *pq, *pk, *pv, *pattno, *ptmp, *px1, *pmoe;
    cudaGetSymbolAddress((void**)&pq, g_q);
    cudaGetSymbolAddress((void**)&pk, g_k);
    cudaGetSymbolAddress((void**)&pv, g_v);
    cudaGetSymbolAddress((void**)&pattno, g_attno);
    cudaGetSymbolAddress((void**)&ptmp, g_tmp);
    cudaGetSymbolAddress((void**)&px1, g_x1);
    cudaGetSymbolAddress((void**)&pmoe, g_moe);

    dim3 gemm_grid(DM / BN, SEQ / BM);   // (12, 32)

    reset_kernel<<<1, 32>>>();

    // QKV projections (fp32 — gating-critical path; q pre-scaled by 1/sqrt(64))
    gemm_kernel<<<gemm_grid, 256>>>(x, Wq, bq, pq, SEQ, DM, DM, nullptr, 0.125f, 1);
    gemm_kernel<<<gemm_grid, 256>>>(x, Wk, bk, pk, SEQ, DM, DM, nullptr, 1.0f, 1);
    gemm_kernel<<<gemm_grid, 256>>>(x, Wv, bv, pv, SEQ, DM, DM, nullptr, 1.0f, 1);

    // sliding-window attention (fp32)
    attn_kernel<<<dim3(SEQ / 64, NH), 256>>>(pattno);

    // Wo projection + residual(hidden) -> LN1 -> x1 (fp32)
    gemm_kernel<<<gemm_grid, 256>>>(pattno, Wo, bo, ptmp, SEQ, DM, DM, x, 1.0f, 2);
    ln_kernel<<<SEQ, 256>>>(ptmp, ln1g, ln1b, px1);

    // gating (fp32-exact; writes gate_weights output + expert lists)
    gating_kernel<<<SEQ, 256>>>(px1, gateW, gateb, gate_out);

    // MoE expert FFN (tf32 tensor cores, grouped sparse top-2)
    mma_moe_gemm1<<<dim3(FF / BN, SEQ / BM, NE), 256>>>(px1, W1e, b1e);
    mma_moe_gemm2<<<dim3(DM / BN, SEQ / BM, NE), 256>>>(W2e, b2e);
    combine_kernel<<<SEQ, 192>>>();

    // Wd projection (tf32) + residual(x1) -> LN2 -> layer_output
    mma_gemm_res<<<gemm_grid, 256>>>(pmoe, Wd, bd, ptmp, px1, SEQ, DM, DM);
    ln_kernel<<<SEQ, 256>>>(ptmp, ln2g, ln2b, out);
}

// round 5
// speedup vs baseline: 1.5839x; 1.0002x over previous
#include <cuda_runtime.h>
#include <math.h>

#define SEQ 4096
#define DM  768
#define NH  12
#define DH  64
#define FF  3072
#define NE  7
#define WIN 256
#define CAP 4096

// ---------------- scratch (static device globals; no allocation) ----------------
__device__ float g_q[NH * SEQ * DH];
__device__ float g_k[NH * SEQ * DH];
__device__ float g_v[NH * SEQ * DH];
__device__ float g_attno[SEQ * DM];
__device__ float g_tmp[SEQ * DM];
__device__ float g_x1[SEQ * DM];
__device__ float g_moe[SEQ * DM];
__device__ float g_h[NE * CAP * FF];     // 352 MB
__device__ float g_eo[NE * CAP * DM];    // 88 MB
__device__ int   g_cnt[NE];
__device__ int   g_tok[NE * CAP];
__device__ float g_wl[NE * CAP];
__device__ int   g_pos[SEQ * 2];

// ---------------- reset ----------------
__global__ void reset_kernel() {
    if (threadIdx.x < NE) g_cnt[threadIdx.x] = 0;
}

// ======================================================================
// fp32 SIMT GEMM (kept for the gating-critical path: QKV, Wo)
// ======================================================================
#define BM 128
#define BN 64
#define BK 16

__global__ __launch_bounds__(256) void gemm_kernel(
    const float* __restrict__ A, const float* __restrict__ B,
    const float* __restrict__ bias, float* __restrict__ C,
    int M, int N, int K, const float* __restrict__ residual,
    float scale, int mode)
{
    __shared__ float As[BK][BM];
    __shared__ float Bs[BK][BN];
    int tid = threadIdx.x;
    int m0 = blockIdx.y * BM;
    int n0 = blockIdx.x * BN;
    int rg = tid >> 4;
    int cg = tid & 15;
    int ar = tid >> 2;
    int ac = (tid & 3) << 2;
    int br = tid >> 4;
    int bc = (tid & 15) << 2;

    float acc[8][4];
#pragma unroll
    for (int i = 0; i < 8; i++)
#pragma unroll
        for (int j = 0; j < 4; j++) acc[i][j] = 0.f;

    for (int k0 = 0; k0 < K; k0 += BK) {
#pragma unroll
        for (int it = 0; it < 2; it++) {
            int r = ar + it * 64;
            float4 av = *(const float4*)&A[(size_t)(m0 + r) * K + k0 + ac];
            As[ac + 0][r] = av.x;
            As[ac + 1][r] = av.y;
            As[ac + 2][r] = av.z;
            As[ac + 3][r] = av.w;
        }
        float4 bv = *(const float4*)&B[(size_t)(k0 + br) * N + n0 + bc];
        *(float4*)&Bs[br][bc] = bv;
        __syncthreads();
#pragma unroll
        for (int k = 0; k < BK; k++) {
            float4 a0 = *(const float4*)&As[k][rg * 8];
            float4 a1 = *(const float4*)&As[k][rg * 8 + 4];
            float4 b0 = *(const float4*)&Bs[k][cg * 4];
            float a[8] = {a0.x, a0.y, a0.z, a0.w, a1.x, a1.y, a1.z, a1.w};
            float b[4] = {b0.x, b0.y, b0.z, b0.w};
#pragma unroll
            for (int i = 0; i < 8; i++)
#pragma unroll
                for (int j = 0; j < 4; j++) acc[i][j] += a[i] * b[j];
        }
        __syncthreads();
    }

#pragma unroll
    for (int i = 0; i < 8; i++) {
        int row = m0 + rg * 8 + i;
#pragma unroll
        for (int j = 0; j < 4; j++) {
            int col = n0 + cg * 4 + j;
            float v = acc[i][j] + bias[col];
            if (mode == 0) {
                C[(size_t)row * N + col] = v;
            } else if (mode == 1) {
                C[((size_t)(col >> 6) * M + row) * 64 + (col & 63)] = v * scale;
            } else {
                C[(size_t)row * N + col] = v + residual[(size_t)row * N + col];
            }
        }
    }
}

// ======================================================================
// tf32 tensor-core GEMM machinery (mma.sync.m16n8k8)
// BM=128, BN=64, BK=16, 256 threads = 8 warps in 4x2, warp tile 32x32.
// ======================================================================
#define APADM 136   // BM + 8 : conflict-free fragment loads
#define APADN 72    // BN + 8

__device__ __forceinline__ unsigned f2tf(float f) {
    unsigned u;
    asm("cvt.rna.tf32.f32 %0, %1;" : "=r"(u) : "f"(f));
    return u;
}

__device__ __forceinline__ void mma_tf32(float* c, const unsigned* a, const unsigned* b) {
    asm volatile(
        "mma.sync.aligned.m16n8k8.row.col.f32.tf32.tf32.f32 "
        "{%0,%1,%2,%3}, {%4,%5,%6,%7}, {%8,%9}, {%0,%1,%2,%3};"
        : "+f"(c[0]), "+f"(c[1]), "+f"(c[2]), "+f"(c[3])
        : "r"(a[0]), "r"(a[1]), "r"(a[2]), "r"(a[3]),
          "r"(b[0]), "r"(b[1]));
}

// shared mainloop body: fills acc[2][4][4] for this block/warp
// A_loader: lambda-free — implemented via macro parameters in each kernel
#define MMA_DECLS()                                                        \
    __shared__ unsigned As[BK][APADM];                                     \
    __shared__ unsigned Bs[BK][APADN];                                     \
    int tid = threadIdx.x;                                                 \
    int ar = tid >> 2, ac = (tid & 3) << 2;                                \
    int br = tid >> 4, bc = (tid & 15) << 2;                               \
    int w = tid >> 5, lane = tid & 31;                                     \
    int m0w = (w >> 1) * 32, n0w = (w & 1) * 32;                           \
    int g = lane >> 2, t = lane & 3;                                       \
    float acc[2][4][4];                                                    \
    _Pragma("unroll")                                                      \
    for (int mi = 0; mi < 2; mi++)                                         \
        _Pragma("unroll")                                                  \
        for (int ni = 0; ni < 4; ni++)                                     \
            _Pragma("unroll")                                              \
            for (int j = 0; j < 4; j++) acc[mi][ni][j] = 0.f;

#define MMA_COMPUTE()                                                      \
    __syncthreads();                                                       \
    _Pragma("unroll")                                                      \
    for (int kk = 0; kk < BK; kk += 8) {                                   \
        unsigned afr[2][4], bfr[4][2];                                     \
        _Pragma("unroll")                                                  \
        for (int mi = 0; mi < 2; mi++) {                                   \
            int mb = m0w + mi * 16 + g;                                    \
            afr[mi][0] = As[kk + t][mb];                                   \
            afr[mi][1] = As[kk + t][mb + 8];                               \
            afr[mi][2] = As[kk + t + 4][mb];                               \
            afr[mi][3] = As[kk + t + 4][mb + 8];                           \
        }                                                                  \
        _Pragma("unroll")                                                  \
        for (int ni = 0; ni < 4; ni++) {                                   \
            int nb = n0w + ni * 8 + g;                                     \
            bfr[ni][0] = Bs[kk + t][nb];                                   \
            bfr[ni][1] = Bs[kk + t + 4][nb];                               \
        }                                                                  \
        _Pragma("unroll")                                                  \
        for (int mi = 0; mi < 2; mi++)                                     \
            _Pragma("unroll")                                              \
            for (int ni = 0; ni < 4; ni++)                                 \
                mma_tf32(acc[mi][ni], afr[mi], bfr[ni]);                   \
    }                                                                      \
    __syncthreads();

// ---------------- MoE GEMM 1 (tf32): gather + GELU ----------------
__global__ __launch_bounds__(256) void mma_moe_gemm1(
    const float* __restrict__ X, const float* __restrict__ W1,
    const float* __restrict__ b1)
{
    int e = blockIdx.z;
    int M = g_cnt[e];
    int m0 = blockIdx.y * BM;
    if (m0 >= M) return;
    const float* B = W1 + (size_t)e * DM * FF;
    const float* bias = b1 + (size_t)e * FF;
    float* C = g_h + (size_t)e * CAP * FF;
    const int* tl = g_tok + e * CAP;
    int n0 = blockIdx.x * BN;

    MMA_DECLS();

    for (int k0 = 0; k0 < DM; k0 += BK) {
#pragma unroll
        for (int it = 0; it < 2; it++) {
            int r = ar + it * 64;
            int grow = m0 + r;
            float4 av = make_float4(0.f, 0.f, 0.f, 0.f);
            if (grow < M) {
                int trow = tl[grow];
                av = *(const float4*)&X[(size_t)trow * DM + k0 + ac];
            }
            As[ac + 0][r] = f2tf(av.x);
            As[ac + 1][r] = f2tf(av.y);
            As[ac + 2][r] = f2tf(av.z);
            As[ac + 3][r] = f2tf(av.w);
        }
        {
            float4 bv = *(const float4*)&B[(size_t)(k0 + br) * FF + n0 + bc];
            Bs[br][bc + 0] = f2tf(bv.x);
            Bs[br][bc + 1] = f2tf(bv.y);
            Bs[br][bc + 2] = f2tf(bv.z);
            Bs[br][bc + 3] = f2tf(bv.w);
        }
        MMA_COMPUTE();
    }

#pragma unroll
    for (int mi = 0; mi < 2; mi++) {
#pragma unroll
        for (int ni = 0; ni < 4; ni++) {
            int col = n0 + n0w + ni * 8 + 2 * t;
            float bv0 = bias[col], bv1 = bias[col + 1];
#pragma unroll
            for (int half = 0; half < 2; half++) {
                int row = m0 + m0w + mi * 16 + g + half * 8;
                if (row >= M) continue;
                float v0 = acc[mi][ni][half * 2 + 0] + bv0;
                float v1 = acc[mi][ni][half * 2 + 1] + bv1;
                v0 = 0.5f * v0 * (1.f + erff(v0 * 0.70710678118654752f));
                v1 = 0.5f * v1 * (1.f + erff(v1 * 0.70710678118654752f));
                C[(size_t)row * FF + col]     = v0;
                C[(size_t)row * FF + col + 1] = v1;
            }
        }
    }
}

// ---------------- MoE GEMM 2 (tf32): * gate weight ----------------
__global__ __launch_bounds__(256) void mma_moe_gemm2(
    const float* __restrict__ W2, const float* __restrict__ b2)
{
    int e = blockIdx.z;
    int M = g_cnt[e];
    int m0 = blockIdx.y * BM;
    if (m0 >= M) return;
    const float* A = g_h + (size_t)e * CAP * FF;
    const float* B = W2 + (size_t)e * FF * DM;
    const float* bias = b2 + (size_t)e * DM;
    const float* wl = g_wl + e * CAP;
    float* C = g_eo + (size_t)e * CAP * DM;
    int n0 = blockIdx.x * BN;

    MMA_DECLS();

    for (int k0 = 0; k0 < FF; k0 += BK) {
#pragma unroll
        for (int it = 0; it < 2; it++) {
            int r = ar + it * 64;
            int grow = m0 + r;
            float4 av = make_float4(0.f, 0.f, 0.f, 0.f);
            if (grow < M) av = *(const float4*)&A[(size_t)grow * FF + k0 + ac];
            As[ac + 0][r] = f2tf(av.x);
            As[ac + 1][r] = f2tf(av.y);
            As[ac + 2][r] = f2tf(av.z);
            As[ac + 3][r] = f2tf(av.w);
        }
        {
            float4 bv = *(const float4*)&B[(size_t)(k0 + br) * DM + n0 + bc];
            Bs[br][bc + 0] = f2tf(bv.x);
            Bs[br][bc + 1] = f2tf(bv.y);
            Bs[br][bc + 2] = f2tf(bv.z);
            Bs[br][bc + 3] = f2tf(bv.w);
        }
        MMA_COMPUTE();
    }

#pragma unroll
    for (int mi = 0; mi < 2; mi++) {
#pragma unroll
        for (int ni = 0; ni < 4; ni++) {
            int col = n0 + n0w + ni * 8 + 2 * t;
            float bv0 = bias[col], bv1 = bias[col + 1];
#pragma unroll
            for (int half = 0; half < 2; half++) {
                int row = m0 + m0w + mi * 16 + g + half * 8;
                if (row >= M) continue;
                float wv = wl[row];
                C[(size_t)row * DM + col]     = (acc[mi][ni][half * 2 + 0] + bv0) * wv;
                C[(size_t)row * DM + col + 1] = (acc[mi][ni][half * 2 + 1] + bv1) * wv;
            }
        }
    }
}

// ---------------- Wd GEMM (tf32): + bias + residual ----------------
__global__ __launch_bounds__(256) void mma_gemm_res(
    const float* __restrict__ A, const float* __restrict__ B,
    const float* __restrict__ bias, float* __restrict__ C,
    const float* __restrict__ R, int M, int N, int K)
{
    int m0 = blockIdx.y * BM;
    int n0 = blockIdx.x * BN;

    MMA_DECLS();

    for (int k0 = 0; k0 < K; k0 += BK) {
#pragma unroll
        for (int it = 0; it < 2; it++) {
            int r = ar + it * 64;
            float4 av = *(const float4*)&A[(size_t)(m0 + r) * K + k0 + ac];
            As[ac + 0][r] = f2tf(av.x);
            As[ac + 1][r] = f2tf(av.y);
            As[ac + 2][r] = f2tf(av.z);
            As[ac + 3][r] = f2tf(av.w);
        }
        {
            float4 bv = *(const float4*)&B[(size_t)(k0 + br) * N + n0 + bc];
            Bs[br][bc + 0] = f2tf(bv.x);
            Bs[br][bc + 1] = f2tf(bv.y);
            Bs[br][bc + 2] = f2tf(bv.z);
            Bs[br][bc + 3] = f2tf(bv.w);
        }
        MMA_COMPUTE();
    }

#pragma unroll
    for (int mi = 0; mi < 2; mi++) {
#pragma unroll
        for (int ni = 0; ni < 4; ni++) {
            int col = n0 + n0w + ni * 8 + 2 * t;
            float bv0 = bias[col], bv1 = bias[col + 1];
#pragma unroll
            for (int half = 0; half < 2; half++) {
                int row = m0 + m0w + mi * 16 + g + half * 8;
                size_t idx = (size_t)row * N + col;
                C[idx]     = acc[mi][ni][half * 2 + 0] + bv0 + R[idx];
                C[idx + 1] = acc[mi][ni][half * 2 + 1] + bv1 + R[idx + 1];
            }
        }
    }
}

// ---------------- fused sliding-window attention ----------------
#define APAD 68
__global__ __launch_bounds__(256) void attn_kernel(float* __restrict__ out)
{
    __shared__ float Qs[64][APAD];
    __shared__ float Ks[32][APAD];
    __shared__ float Vs[32][APAD];
    __shared__ float Ss[64][33];
    __shared__ float mS[64], lS[64], cS[64];

    int h = blockIdx.y;
    int q0 = blockIdx.x * 64;
    int tid = threadIdx.x;
    int q = tid & 63;
    int kg = tid >> 6;
    int dp = tid >> 6;

    const float* qhead = g_q + (size_t)h * SEQ * DH;
    const float* khead = g_k + (size_t)h * SEQ * DH;
    const float* vhead = g_v + (size_t)h * SEQ * DH;

#pragma unroll
    for (int i = 0; i < 4; i++) {
        int idx = tid + i * 256;
        int r = idx >> 4;
        int c = (idx & 15) << 2;
        float4 v = *(const float4*)&qhead[(size_t)(q0 + r) * DH + c];
        *(float4*)&Qs[r][c] = v;
    }
    if (tid < 64) { mS[tid] = -1e9f; lS[tid] = 0.f; }

    float acc[16];
#pragma unroll
    for (int i = 0; i < 16; i++) acc[i] = 0.f;
    __syncthreads();

    for (int kt = 0; kt < 18; kt++) {
        int kbase = q0 - 256 + kt * 32;
        if (kbase + 31 < 0 || kbase >= SEQ) continue;

#pragma unroll
        for (int i = 0; i < 2; i++) {
            int idx = tid + i * 256;
            int r = idx >> 4;
            int c = (idx & 15) << 2;
            int kpos = kbase + r;
            float4 kv = make_float4(0.f, 0.f, 0.f, 0.f);
            float4 vv = kv;
            if (kpos >= 0 && kpos < SEQ) {
                kv = *(const float4*)&khead[(size_t)kpos * DH + c];
                vv = *(const float4*)&vhead[(size_t)kpos * DH + c];
            }
            *(float4*)&Ks[r][c] = kv;
            *(float4*)&Vs[r][c] = vv;
        }
        __syncthreads();

        float s[8];
#pragma unroll
        for (int j = 0; j < 8; j++) s[j] = 0.f;
#pragma unroll
        for (int d = 0; d < 64; d += 4) {
            float4 q4 = *(const float4*)&Qs[q][d];
#pragma unroll
            for (int j = 0; j < 8; j++) {
                float4 k4 = *(const float4*)&Ks[kg * 8 + j][d];
                s[j] += q4.x * k4.x + q4.y * k4.y + q4.z * k4.z + q4.w * k4.w;
            }
        }
        int qpos = q0 + q;
#pragma unroll
        for (int j = 0; j < 8; j++) {
            int kpos = kbase + kg * 8 + j;
            bool valid = (kpos >= 0) && (kpos < SEQ) &&
                         (kpos >= qpos - WIN) && (kpos <= qpos + WIN);
            Ss[q][kg * 8 + j] = valid ? s[j] : -1e9f;
        }
        __syncthreads();

        if (tid < 64) {
            int r = tid;
            float mold = mS[r];
            float tmax = -1e9f;
#pragma unroll
            for (int kk = 0; kk < 32; kk++) tmax = fmaxf(tmax, Ss[r][kk]);
            float mnew = fmaxf(mold, tmax);
            float corr = __expf(mold - mnew);
            float sum = 0.f;
#pragma unroll
            for (int kk = 0; kk < 32; kk++) {
                float p = __expf(Ss[r][kk] - mnew);
                Ss[r][kk] = p;
                sum += p;
            }
            lS[r] = lS[r] * corr + sum;
            mS[r] = mnew;
            cS[r] = corr;
        }
        __syncthreads();

        float corr = cS[q];
#pragma unroll
        for (int i = 0; i < 16; i++) acc[i] *= corr;
#pragma unroll
        for (int kk = 0; kk < 32; kk++) {
            float p = Ss[q][kk];
#pragma unroll
            for (int i4 = 0; i4 < 4; i4++) {
                float4 v4 = *(const float4*)&Vs[kk][dp * 16 + i4 * 4];
                acc[i4 * 4 + 0] += p * v4.x;
                acc[i4 * 4 + 1] += p * v4.y;
                acc[i4 * 4 + 2] += p * v4.z;
                acc[i4 * 4 + 3] += p * v4.w;
            }
        }
        __syncthreads();
    }

    float inv = 1.f / lS[q];
    float* o = out + (size_t)(q0 + q) * DM + h * DH + dp * 16;
#pragma unroll
    for (int i4 = 0; i4 < 4; i4++) {
        float4 v;
        v.x = acc[i4 * 4 + 0] * inv;
        v.y = acc[i4 * 4 + 1] * inv;
        v.z = acc[i4 * 4 + 2] * inv;
        v.w = acc[i4 * 4 + 3] * inv;
        *(float4*)&o[i4 * 4] = v;
    }
}

// ---------------- layer norm (row-wise) ----------------
__global__ __launch_bounds__(256) void ln_kernel(
    const float* __restrict__ in, const float* __restrict__ g,
    const float* __restrict__ b, float* __restrict__ out)
{
    __shared__ float rs[8], rs2[8];
    int row = blockIdx.x;
    int tid = threadIdx.x;
    const float* x = in + (size_t)row * DM;
    float vals[3];
    float s = 0.f, s2 = 0.f;
#pragma unroll
    for (int i = 0; i < 3; i++) {
        float v = x[tid + i * 256];
        vals[i] = v;
        s += v;
        s2 += v * v;
    }
    int lane = tid & 31, w = tid >> 5;
#pragma unroll
    for (int o = 16; o; o >>= 1) {
        s += __shfl_down_sync(0xffffffffu, s, o);
        s2 += __shfl_down_sync(0xffffffffu, s2, o);
    }
    if (lane == 0) { rs[w] = s; rs2[w] = s2; }
    __syncthreads();
    if (tid == 0) {
        float a = 0.f, c = 0.f;
#pragma unroll
        for (int i = 0; i < 8; i++) { a += rs[i]; c += rs2[i]; }
        rs[0] = a;
        rs2[0] = c;
    }
    __syncthreads();
    float mean = rs[0] * (1.f / DM);
    float var = rs2[0] * (1.f / DM) - mean * mean;
    float rstd = rsqrtf(var + 1e-5f);
    float* o = out + (size_t)row * DM;
#pragma unroll
    for (int i = 0; i < 3; i++) {
        int col = tid + i * 256;
        o[col] = (vals[i] - mean) * rstd * g[col] + b[col];
    }
}

// ---------------- gating: logits, top-2, softmax, expert lists ----------------
__global__ __launch_bounds__(256) void gating_kernel(
    const float* __restrict__ x1, const float* __restrict__ gW,
    const float* __restrict__ gb, float* __restrict__ gate_out)
{
    __shared__ float xs[DM];
    __shared__ float lg[8];
    int row = blockIdx.x;
    int tid = threadIdx.x;
    for (int i = tid; i < DM; i += 256) xs[i] = x1[(size_t)row * DM + i];
    __syncthreads();
    int w = tid >> 5, lane = tid & 31;
    if (w < NE) {
        float p = 0.f;
        for (int d = lane; d < DM; d += 32) p += xs[d] * gW[d * NE + w];
#pragma unroll
        for (int o = 16; o; o >>= 1) p += __shfl_down_sync(0xffffffffu, p, o);
        if (lane == 0) lg[w] = p + gb[w];
    }
    __syncthreads();
    if (tid == 0) {
        int e1 = 0;
        float v1 = lg[0];
        for (int e = 1; e < NE; e++)
            if (lg[e] > v1) { v1 = lg[e]; e1 = e; }
        int e2 = -1;
        float v2 = -1e30f;
        for (int e = 0; e < NE; e++) {
            if (e == e1) continue;
            if (lg[e] > v2) { v2 = lg[e]; e2 = e; }
        }
        float z = expf(v2 - v1);
        float w1 = 1.f / (1.f + z);
        float w2 = z / (1.f + z);
        float* go = gate_out + (size_t)row * NE;
#pragma unroll
        for (int e = 0; e < NE; e++) go[e] = 0.f;
        go[e1] = w1;
        go[e2] = w2;
        int s1 = atomicAdd(&g_cnt[e1], 1);
        g_tok[e1 * CAP + s1] = row;
        g_wl[e1 * CAP + s1] = w1;
        g_pos[row * 2 + 0] = e1 * CAP + s1;
        int s2 = atomicAdd(&g_cnt[e2], 1);
        g_tok[e2 * CAP + s2] = row;
        g_wl[e2 * CAP + s2] = w2;
        g_pos[row * 2 + 1] = e2 * CAP + s2;
    }
}

// ---------------- combine two expert outputs per token ----------------
__global__ __launch_bounds__(192) void combine_kernel()
{
    int t = blockIdx.x;
    int p0 = g_pos[t * 2 + 0];
    int p1 = g_pos[t * 2 + 1];
    const float* a = g_eo + (size_t)p0 * DM;
    const float* b = g_eo + (size_t)p1 * DM;
    float* o = g_moe + (size_t)t * DM;
    int i = threadIdx.x * 4;
    float4 av = *(const float4*)&a[i];
    float4 bv = *(const float4*)&b[i];
    float4 v;
    v.x = av.x + bv.x;
    v.y = av.y + bv.y;
    v.z = av.z + bv.z;
    v.w = av.w + bv.w;
    *(float4*)&o[i] = v;
}

// ---------------- launch ----------------
extern "C" void kernel_launch(void* const* d_in, const int* in_sizes, int n_in,
                              void* d_out, int out_size)
{
    (void)in_sizes; (void)n_in; (void)out_size;
    const float* x     = (const float*)d_in[0];
    const float* Wq    = (const float*)d_in[1];
    const float* bq    = (const float*)d_in[2];
    const float* Wk    = (const float*)d_in[3];
    const float* bk    = (const float*)d_in[4];
    const float* Wv    = (const float*)d_in[5];
    const float* bv    = (const float*)d_in[6];
    const float* Wo    = (const float*)d_in[7];
    const float* bo    = (const float*)d_in[8];
    const float* ln1g  = (const float*)d_in[9];
    const float* ln1b  = (const float*)d_in[10];
    const float* gateW = (const float*)d_in[11];
    const float* gateb = (const float*)d_in[12];
    const float* W1e   = (const float*)d_in[13];
    const float* b1e   = (const float*)d_in[14];
    const float* W2e   = (const float*)d_in[15];
    const float* b2e   = (const float*)d_in[16];
    const float* Wd    = (const float*)d_in[17];
    const float* bd    = (const float*)d_in[18];
    const float* ln2g  = (const float*)d_in[19];
    const float* ln2b  = (const float*)d_in[20];

    float* out = (float*)d_out;
    float* gate_out = out + (size_t)SEQ * DM;

    float *pq, *pk, *pv, *pattno, *ptmp, *px1, *pmoe;
    cudaGetSymbolAddress((void**)&pq, g_q);
    cudaGetSymbolAddress((void**)&pk, g_k);
    cudaGetSymbolAddress((void**)&pv, g_v);
    cudaGetSymbolAddress((void**)&pattno, g_attno);
    cudaGetSymbolAddress((void**)&ptmp, g_tmp);
    cudaGetSymbolAddress((void**)&px1, g_x1);
    cudaGetSymbolAddress((void**)&pmoe, g_moe);

    dim3 gemm_grid(DM / BN, SEQ / BM);   // (12, 32)

    reset_kernel<<<1, 32>>>();

    // QKV projections (fp32 — gating-critical path; q pre-scaled by 1/sqrt(64))
    gemm_kernel<<<gemm_grid, 256>>>(x, Wq, bq, pq, SEQ, DM, DM, nullptr, 0.125f, 1);
    gemm_kernel<<<gemm_grid, 256>>>(x, Wk, bk, pk, SEQ, DM, DM, nullptr, 1.0f, 1);
    gemm_kernel<<<gemm_grid, 256>>>(x, Wv, bv, pv, SEQ, DM, DM, nullptr, 1.0f, 1);

    // sliding-window attention (fp32)
    attn_kernel<<<dim3(SEQ / 64, NH), 256>>>(pattno);

    // Wo projection + residual(hidden) -> LN1 -> x1 (fp32)
    gemm_kernel<<<gemm_grid, 256>>>(pattno, Wo, bo, ptmp, SEQ, DM, DM, x, 1.0f, 2);
    ln_kernel<<<SEQ, 256>>>(ptmp, ln1g, ln1b, px1);

    // gating (fp32-exact; writes gate_weights output + expert lists)
    gating_kernel<<<SEQ, 256>>>(px1, gateW, gateb, gate_out);

    // MoE expert FFN (tf32 tensor cores, grouped sparse top-2)
    mma_moe_gemm1<<<dim3(FF / BN, SEQ / BM, NE), 256>>>(px1, W1e, b1e);
    mma_moe_gemm2<<<dim3(DM / BN, SEQ / BM, NE), 256>>>(W2e, b2e);
    combine_kernel<<<SEQ, 192>>>();

    // Wd projection (tf32) + residual(x1) -> LN2 -> layer_output
    mma_gemm_res<<<gemm_grid, 256>>>(pmoe, Wd, bd, ptmp, px1, SEQ, DM, DM);
    ln_kernel<<<SEQ, 256>>>(ptmp, ln2g, ln2b, out);
}

// round 6
// speedup vs baseline: 1.5865x; 1.0016x over previous
#include <cuda_runtime.h>
#include <math.h>

#define SEQ 4096
#define DM  768
#define NH  12
#define DH  64
#define FF  3072
#define NE  7
#define WIN 256
#define CAP 4096

// ---------------- scratch (static device globals; no allocation) ----------------
__device__ float g_q[NH * SEQ * DH];
__device__ float g_k[NH * SEQ * DH];
__device__ float g_v[NH * SEQ * DH];
__device__ float g_attno[SEQ * DM];
__device__ float g_tmp[SEQ * DM];
__device__ float g_x1[SEQ * DM];
__device__ float g_moe[SEQ * DM];
__device__ float g_h[NE * CAP * FF];     // 352 MB
__device__ float g_eo[NE * CAP * DM];    // 88 MB
__device__ int   g_cnt[NE];
__device__ int   g_tok[NE * CAP];
__device__ float g_wl[NE * CAP];
__device__ int   g_pos[SEQ * 2];

// ---------------- reset ----------------
__global__ void reset_kernel() {
    if (threadIdx.x < NE) g_cnt[threadIdx.x] = 0;
}

// ======================================================================
// fp32 SIMT GEMM (kept for the gating-critical path: QKV, Wo)
// ======================================================================
#define BM 128
#define BN 64
#define BK 16

__global__ __launch_bounds__(256) void gemm_kernel(
    const float* __restrict__ A, const float* __restrict__ B,
    const float* __restrict__ bias, float* __restrict__ C,
    int M, int N, int K, const float* __restrict__ residual,
    float scale, int mode)
{
    __shared__ float As[BK][BM];
    __shared__ float Bs[BK][BN];
    int tid = threadIdx.x;
    int m0 = blockIdx.y * BM;
    int n0 = blockIdx.x * BN;
    int rg = tid >> 4;
    int cg = tid & 15;
    int ar = tid >> 2;
    int ac = (tid & 3) << 2;
    int br = tid >> 4;
    int bc = (tid & 15) << 2;

    float acc[8][4];
#pragma unroll
    for (int i = 0; i < 8; i++)
#pragma unroll
        for (int j = 0; j < 4; j++) acc[i][j] = 0.f;

    for (int k0 = 0; k0 < K; k0 += BK) {
#pragma unroll
        for (int it = 0; it < 2; it++) {
            int r = ar + it * 64;
            float4 av = *(const float4*)&A[(size_t)(m0 + r) * K + k0 + ac];
            As[ac + 0][r] = av.x;
            As[ac + 1][r] = av.y;
            As[ac + 2][r] = av.z;
            As[ac + 3][r] = av.w;
        }
        float4 bv = *(const float4*)&B[(size_t)(k0 + br) * N + n0 + bc];
        *(float4*)&Bs[br][bc] = bv;
        __syncthreads();
#pragma unroll
        for (int k = 0; k < BK; k++) {
            float4 a0 = *(const float4*)&As[k][rg * 8];
            float4 a1 = *(const float4*)&As[k][rg * 8 + 4];
            float4 b0 = *(const float4*)&Bs[k][cg * 4];
            float a[8] = {a0.x, a0.y, a0.z, a0.w, a1.x, a1.y, a1.z, a1.w};
            float b[4] = {b0.x, b0.y, b0.z, b0.w};
#pragma unroll
            for (int i = 0; i < 8; i++)
#pragma unroll
                for (int j = 0; j < 4; j++) acc[i][j] += a[i] * b[j];
        }
        __syncthreads();
    }

#pragma unroll
    for (int i = 0; i < 8; i++) {
        int row = m0 + rg * 8 + i;
#pragma unroll
        for (int j = 0; j < 4; j++) {
            int col = n0 + cg * 4 + j;
            float v = acc[i][j] + bias[col];
            if (mode == 0) {
                C[(size_t)row * N + col] = v;
            } else if (mode == 1) {
                C[((size_t)(col >> 6) * M + row) * 64 + (col & 63)] = v * scale;
            } else {
                C[(size_t)row * N + col] = v + residual[(size_t)row * N + col];
            }
        }
    }
}

// ======================================================================
// tf32 tensor-core GEMM machinery (mma.sync.m16n8k8)
// BM=128, BN=64, BK=16, 256 threads = 8 warps in 4x2, warp tile 32x32.
// ======================================================================
#define APADM 136   // BM + 8 : conflict-free fragment loads
#define APADN 72    // BN + 8

__device__ __forceinline__ unsigned f2tf(float f) {
    unsigned u;
    asm("cvt.rna.tf32.f32 %0, %1;" : "=r"(u) : "f"(f));
    return u;
}

__device__ __forceinline__ void mma_tf32(float* c, const unsigned* a, const unsigned* b) {
    asm volatile(
        "mma.sync.aligned.m16n8k8.row.col.f32.tf32.tf32.f32 "
        "{%0,%1,%2,%3}, {%4,%5,%6,%7}, {%8,%9}, {%0,%1,%2,%3};"
        : "+f"(c[0]), "+f"(c[1]), "+f"(c[2]), "+f"(c[3])
        : "r"(a[0]), "r"(a[1]), "r"(a[2]), "r"(a[3]),
          "r"(b[0]), "r"(b[1]));
}

// shared mainloop body: fills acc[2][4][4] for this block/warp
// A_loader: lambda-free — implemented via macro parameters in each kernel
#define MMA_DECLS()                                                        \
    __shared__ unsigned As[BK][APADM];                                     \
    __shared__ unsigned Bs[BK][APADN];                                     \
    int tid = threadIdx.x;                                                 \
    int ar = tid >> 2, ac = (tid & 3) << 2;                                \
    int br = tid >> 4, bc = (tid & 15) << 2;                               \
    int w = tid >> 5, lane = tid & 31;                                     \
    int m0w = (w >> 1) * 32, n0w = (w & 1) * 32;                           \
    int g = lane >> 2, t = lane & 3;                                       \
    float acc[2][4][4];                                                    \
    _Pragma("unroll")                                                      \
    for (int mi = 0; mi < 2; mi++)                                         \
        _Pragma("unroll")                                                  \
        for (int ni = 0; ni < 4; ni++)                                     \
            _Pragma("unroll")                                              \
            for (int j = 0; j < 4; j++) acc[mi][ni][j] = 0.f;

#define MMA_COMPUTE()                                                      \
    __syncthreads();                                                       \
    _Pragma("unroll")                                                      \
    for (int kk = 0; kk < BK; kk += 8) {                                   \
        unsigned afr[2][4], bfr[4][2];                                     \
        _Pragma("unroll")                                                  \
        for (int mi = 0; mi < 2; mi++) {                                   \
            int mb = m0w + mi * 16 + g;                                    \
            afr[mi][0] = As[kk + t][mb];                                   \
            afr[mi][1] = As[kk + t][mb + 8];                               \
            afr[mi][2] = As[kk + t + 4][mb];                               \
            afr[mi][3] = As[kk + t + 4][mb + 8];                           \
        }                                                                  \
        _Pragma("unroll")                                                  \
        for (int ni = 0; ni < 4; ni++) {                                   \
            int nb = n0w + ni * 8 + g;                                     \
            bfr[ni][0] = Bs[kk + t][nb];                                   \
            bfr[ni][1] = Bs[kk + t + 4][nb];                               \
        }                                                                  \
        _Pragma("unroll")                                                  \
        for (int mi = 0; mi < 2; mi++)                                     \
            _Pragma("unroll")                                              \
            for (int ni = 0; ni < 4; ni++)                                 \
                mma_tf32(acc[mi][ni], afr[mi], bfr[ni]);                   \
    }                                                                      \
    __syncthreads();

// ---------------- MoE GEMM 1 (tf32): gather + GELU ----------------
__global__ __launch_bounds__(256) void mma_moe_gemm1(
    const float* __restrict__ X, const float* __restrict__ W1,
    const float* __restrict__ b1)
{
    int e = blockIdx.z;
    int M = g_cnt[e];
    int m0 = blockIdx.y * BM;
    if (m0 >= M) return;
    const float* B = W1 + (size_t)e * DM * FF;
    const float* bias = b1 + (size_t)e * FF;
    float* C = g_h + (size_t)e * CAP * FF;
    const int* tl = g_tok + e * CAP;
    int n0 = blockIdx.x * BN;

    MMA_DECLS();

    for (int k0 = 0; k0 < DM; k0 += BK) {
#pragma unroll
        for (int it = 0; it < 2; it++) {
            int r = ar + it * 64;
            int grow = m0 + r;
            float4 av = make_float4(0.f, 0.f, 0.f, 0.f);
            if (grow < M) {
                int trow = tl[grow];
                av = *(const float4*)&X[(size_t)trow * DM + k0 + ac];
            }
            As[ac + 0][r] = f2tf(av.x);
            As[ac + 1][r] = f2tf(av.y);
            As[ac + 2][r] = f2tf(av.z);
            As[ac + 3][r] = f2tf(av.w);
        }
        {
            float4 bv = *(const float4*)&B[(size_t)(k0 + br) * FF + n0 + bc];
            Bs[br][bc + 0] = f2tf(bv.x);
            Bs[br][bc + 1] = f2tf(bv.y);
            Bs[br][bc + 2] = f2tf(bv.z);
            Bs[br][bc + 3] = f2tf(bv.w);
        }
        MMA_COMPUTE();
    }

#pragma unroll
    for (int mi = 0; mi < 2; mi++) {
#pragma unroll
        for (int ni = 0; ni < 4; ni++) {
            int col = n0 + n0w + ni * 8 + 2 * t;
            float bv0 = bias[col], bv1 = bias[col + 1];
#pragma unroll
            for (int half = 0; half < 2; half++) {
                int row = m0 + m0w + mi * 16 + g + half * 8;
                if (row >= M) continue;
                float v0 = acc[mi][ni][half * 2 + 0] + bv0;
                float v1 = acc[mi][ni][half * 2 + 1] + bv1;
                v0 = 0.5f * v0 * (1.f + erff(v0 * 0.70710678118654752f));
                v1 = 0.5f * v1 * (1.f + erff(v1 * 0.70710678118654752f));
                C[(size_t)row * FF + col]     = v0;
                C[(size_t)row * FF + col + 1] = v1;
            }
        }
    }
}

// ---------------- MoE GEMM 2 (tf32): * gate weight ----------------
__global__ __launch_bounds__(256) void mma_moe_gemm2(
    const float* __restrict__ W2, const float* __restrict__ b2)
{
    int e = blockIdx.z;
    int M = g_cnt[e];
    int m0 = blockIdx.y * BM;
    if (m0 >= M) return;
    const float* A = g_h + (size_t)e * CAP * FF;
    const float* B = W2 + (size_t)e * FF * DM;
    const float* bias = b2 + (size_t)e * DM;
    const float* wl = g_wl + e * CAP;
    float* C = g_eo + (size_t)e * CAP * DM;
    int n0 = blockIdx.x * BN;

    MMA_DECLS();

    for (int k0 = 0; k0 < FF; k0 += BK) {
#pragma unroll
        for (int it = 0; it < 2; it++) {
            int r = ar + it * 64;
            int grow = m0 + r;
            float4 av = make_float4(0.f, 0.f, 0.f, 0.f);
            if (grow < M) av = *(const float4*)&A[(size_t)grow * FF + k0 + ac];
            As[ac + 0][r] = f2tf(av.x);
            As[ac + 1][r] = f2tf(av.y);
            As[ac + 2][r] = f2tf(av.z);
            As[ac + 3][r] = f2tf(av.w);
        }
        {
            float4 bv = *(const float4*)&B[(size_t)(k0 + br) * DM + n0 + bc];
            Bs[br][bc + 0] = f2tf(bv.x);
            Bs[br][bc + 1] = f2tf(bv.y);
            Bs[br][bc + 2] = f2tf(bv.z);
            Bs[br][bc + 3] = f2tf(bv.w);
        }
        MMA_COMPUTE();
    }

#pragma unroll
    for (int mi = 0; mi < 2; mi++) {
#pragma unroll
        for (int ni = 0; ni < 4; ni++) {
            int col = n0 + n0w + ni * 8 + 2 * t;
            float bv0 = bias[col], bv1 = bias[col + 1];
#pragma unroll
            for (int half = 0; half < 2; half++) {
                int row = m0 + m0w + mi * 16 + g + half * 8;
                if (row >= M) continue;
                float wv = wl[row];
                C[(size_t)row * DM + col]     = (acc[mi][ni][half * 2 + 0] + bv0) * wv;
                C[(size_t)row * DM + col + 1] = (acc[mi][ni][half * 2 + 1] + bv1) * wv;
            }
        }
    }
}

// ---------------- Wd GEMM (tf32): + bias + residual ----------------
__global__ __launch_bounds__(256) void mma_gemm_res(
    const float* __restrict__ A, const float* __restrict__ B,
    const float* __restrict__ bias, float* __restrict__ C,
    const float* __restrict__ R, int M, int N, int K)
{
    int m0 = blockIdx.y * BM;
    int n0 = blockIdx.x * BN;

    MMA_DECLS();

    for (int k0 = 0; k0 < K; k0 += BK) {
#pragma unroll
        for (int it = 0; it < 2; it++) {
            int r = ar + it * 64;
            float4 av = *(const float4*)&A[(size_t)(m0 + r) * K + k0 + ac];
            As[ac + 0][r] = f2tf(av.x);
            As[ac + 1][r] = f2tf(av.y);
            As[ac + 2][r] = f2tf(av.z);
            As[ac + 3][r] = f2tf(av.w);
        }
        {
            float4 bv = *(const float4*)&B[(size_t)(k0 + br) * N + n0 + bc];
            Bs[br][bc + 0] = f2tf(bv.x);
            Bs[br][bc + 1] = f2tf(bv.y);
            Bs[br][bc + 2] = f2tf(bv.z);
            Bs[br][bc + 3] = f2tf(bv.w);
        }
        MMA_COMPUTE();
    }

#pragma unroll
    for (int mi = 0; mi < 2; mi++) {
#pragma unroll
        for (int ni = 0; ni < 4; ni++) {
            int col = n0 + n0w + ni * 8 + 2 * t;
            float bv0 = bias[col], bv1 = bias[col + 1];
#pragma unroll
            for (int half = 0; half < 2; half++) {
                int row = m0 + m0w + mi * 16 + g + half * 8;
                size_t idx = (size_t)row * N + col;
                C[idx]     = acc[mi][ni][half * 2 + 0] + bv0 + R[idx];
                C[idx + 1] = acc[mi][ni][half * 2 + 1] + bv1 + R[idx + 1];
            }
        }
    }
}

// ---------------- fused sliding-window attention ----------------
#define APAD 68
__global__ __launch_bounds__(256) void attn_kernel(float* __restrict__ out)
{
    __shared__ float Qs[64][APAD];
    __shared__ float Ks[32][APAD];
    __shared__ float Vs[32][APAD];
    __shared__ float Ss[64][33];
    __shared__ float mS[64], lS[64], cS[64];

    int h = blockIdx.y;
    int q0 = blockIdx.x * 64;
    int tid = threadIdx.x;
    int q = tid & 63;
    int kg = tid >> 6;
    int dp = tid >> 6;

    const float* qhead = g_q + (size_t)h * SEQ * DH;
    const float* khead = g_k + (size_t)h * SEQ * DH;
    const float* vhead = g_v + (size_t)h * SEQ * DH;

#pragma unroll
    for (int i = 0; i < 4; i++) {
        int idx = tid + i * 256;
        int r = idx >> 4;
        int c = (idx & 15) << 2;
        float4 v = *(const float4*)&qhead[(size_t)(q0 + r) * DH + c];
        *(float4*)&Qs[r][c] = v;
    }
    if (tid < 64) { mS[tid] = -1e9f; lS[tid] = 0.f; }

    float acc[16];
#pragma unroll
    for (int i = 0; i < 16; i++) acc[i] = 0.f;
    __syncthreads();

    for (int kt = 0; kt < 18; kt++) {
        int kbase = q0 - 256 + kt * 32;
        if (kbase + 31 < 0 || kbase >= SEQ) continue;

#pragma unroll
        for (int i = 0; i < 2; i++) {
            int idx = tid + i * 256;
            int r = idx >> 4;
            int c = (idx & 15) << 2;
            int kpos = kbase + r;
            float4 kv = make_float4(0.f, 0.f, 0.f, 0.f);
            float4 vv = kv;
            if (kpos >= 0 && kpos < SEQ) {
                kv = *(const float4*)&khead[(size_t)kpos * DH + c];
                vv = *(const float4*)&vhead[(size_t)kpos * DH + c];
            }
            *(float4*)&Ks[r][c] = kv;
            *(float4*)&Vs[r][c] = vv;
        }
        __syncthreads();

        float s[8];
#pragma unroll
        for (int j = 0; j < 8; j++) s[j] = 0.f;
#pragma unroll
        for (int d = 0; d < 64; d += 4) {
            float4 q4 = *(const float4*)&Qs[q][d];
#pragma unroll
            for (int j = 0; j < 8; j++) {
                float4 k4 = *(const float4*)&Ks[kg * 8 + j][d];
                s[j] += q4.x * k4.x + q4.y * k4.y + q4.z * k4.z + q4.w * k4.w;
            }
        }
        int qpos = q0 + q;
#pragma unroll
        for (int j = 0; j < 8; j++) {
            int kpos = kbase + kg * 8 + j;
            bool valid = (kpos >= 0) && (kpos < SEQ) &&
                         (kpos >= qpos - WIN) && (kpos <= qpos + WIN);
            Ss[q][kg * 8 + j] = valid ? s[j] : -1e9f;
        }
        __syncthreads();

        if (tid < 64) {
            int r = tid;
            float mold = mS[r];
            float tmax = -1e9f;
#pragma unroll
            for (int kk = 0; kk < 32; kk++) tmax = fmaxf(tmax, Ss[r][kk]);
            float mnew = fmaxf(mold, tmax);
            float corr = __expf(mold - mnew);
            float sum = 0.f;
#pragma unroll
            for (int kk = 0; kk < 32; kk++) {
                float p = __expf(Ss[r][kk] - mnew);
                Ss[r][kk] = p;
                sum += p;
            }
            lS[r] = lS[r] * corr + sum;
            mS[r] = mnew;
            cS[r] = corr;
        }
        __syncthreads();

        float corr = cS[q];
#pragma unroll
        for (int i = 0; i < 16; i++) acc[i] *= corr;
#pragma unroll
        for (int kk = 0; kk < 32; kk++) {
            float p = Ss[q][kk];
#pragma unroll
            for (int i4 = 0; i4 < 4; i4++) {
                float4 v4 = *(const float4*)&Vs[kk][dp * 16 + i4 * 4];
                acc[i4 * 4 + 0] += p * v4.x;
                acc[i4 * 4 + 1] += p * v4.y;
                acc[i4 * 4 + 2] += p * v4.z;
                acc[i4 * 4 + 3] += p * v4.w;
            }
        }
        __syncthreads();
    }

    float inv = 1.f / lS[q];
    float* o = out + (size_t)(q0 + q) * DM + h * DH + dp * 16;
#pragma unroll
    for (int i4 = 0; i4 < 4; i4++) {
        float4 v;
        v.x = acc[i4 * 4 + 0] * inv;
        v.y = acc[i4 * 4 + 1] * inv;
        v.z = acc[i4 * 4 + 2] * inv;
        v.w = acc[i4 * 4 + 3] * inv;
        *(float4*)&o[i4 * 4] = v;
    }
}

// ---------------- layer norm (row-wise) ----------------
__global__ __launch_bounds__(256) void ln_kernel(
    const float* __restrict__ in, const float* __restrict__ g,
    const float* __restrict__ b, float* __restrict__ out)
{
    __shared__ float rs[8], rs2[8];
    int row = blockIdx.x;
    int tid = threadIdx.x;
    const float* x = in + (size_t)row * DM;
    float vals[3];
    float s = 0.f, s2 = 0.f;
#pragma unroll
    for (int i = 0; i < 3; i++) {
        float v = x[tid + i * 256];
        vals[i] = v;
        s += v;
        s2 += v * v;
    }
    int lane = tid & 31, w = tid >> 5;
#pragma unroll
    for (int o = 16; o; o >>= 1) {
        s += __shfl_down_sync(0xffffffffu, s, o);
        s2 += __shfl_down_sync(0xffffffffu, s2, o);
    }
    if (lane == 0) { rs[w] = s; rs2[w] = s2; }
    __syncthreads();
    if (tid == 0) {
        float a = 0.f, c = 0.f;
#pragma unroll
        for (int i = 0; i < 8; i++) { a += rs[i]; c += rs2[i]; }
        rs[0] = a;
        rs2[0] = c;
    }
    __syncthreads();
    float mean = rs[0] * (1.f / DM);
    float var = rs2[0] * (1.f / DM) - mean * mean;
    float rstd = rsqrtf(var + 1e-5f);
    float* o = out + (size_t)row * DM;
#pragma unroll
    for (int i = 0; i < 3; i++) {
        int col = tid + i * 256;
        o[col] = (vals[i] - mean) * rstd * g[col] + b[col];
    }
}

// ---------------- gating: logits, top-2, softmax, expert lists ----------------
__global__ __launch_bounds__(256) void gating_kernel(
    const float* __restrict__ x1, const float* __restrict__ gW,
    const float* __restrict__ gb, float* __restrict__ gate_out)
{
    __shared__ float xs[DM];
    __shared__ float lg[8];
    int row = blockIdx.x;
    int tid = threadIdx.x;
    for (int i = tid; i < DM; i += 256) xs[i] = x1[(size_t)row * DM + i];
    __syncthreads();
    int w = tid >> 5, lane = tid & 31;
    if (w < NE) {
        float p = 0.f;
        for (int d = lane; d < DM; d += 32) p += xs[d] * gW[d * NE + w];
#pragma unroll
        for (int o = 16; o; o >>= 1) p += __shfl_down_sync(0xffffffffu, p, o);
        if (lane == 0) lg[w] = p + gb[w];
    }
    __syncthreads();
    if (tid == 0) {
        int e1 = 0;
        float v1 = lg[0];
        for (int e = 1; e < NE; e++)
            if (lg[e] > v1) { v1 = lg[e]; e1 = e; }
        int e2 = -1;
        float v2 = -1e30f;
        for (int e = 0; e < NE; e++) {
            if (e == e1) continue;
            if (lg[e] > v2) { v2 = lg[e]; e2 = e; }
        }
        float z = expf(v2 - v1);
        float w1 = 1.f / (1.f + z);
        float w2 = z / (1.f + z);
        float* go = gate_out + (size_t)row * NE;
#pragma unroll
        for (int e = 0; e < NE; e++) go[e] = 0.f;
        go[e1] = w1;
        go[e2] = w2;
        int s1 = atomicAdd(&g_cnt[e1], 1);
        g_tok[e1 * CAP + s1] = row;
        g_wl[e1 * CAP + s1] = w1;
        g_pos[row * 2 + 0] = e1 * CAP + s1;
        int s2 = atomicAdd(&g_cnt[e2], 1);
        g_tok[e2 * CAP + s2] = row;
        g_wl[e2 * CAP + s2] = w2;
        g_pos[row * 2 + 1] = e2 * CAP + s2;
    }
}

// ---------------- combine two expert outputs per token ----------------
__global__ __launch_bounds__(192) void combine_kernel()
{
    int t = blockIdx.x;
    int p0 = g_pos[t * 2 + 0];
    int p1 = g_pos[t * 2 + 1];
    const float* a = g_eo + (size_t)p0 * DM;
    const float* b = g_eo + (size_t)p1 * DM;
    float* o = g_moe + (size_t)t * DM;
    int i = threadIdx.x * 4;
    float4 av = *(const float4*)&a[i];
    float4 bv = *(const float4*)&b[i];
    float4 v;
    v.x = av.x + bv.x;
    v.y = av.y + bv.y;
    v.z = av.z + bv.z;
    v.w = av.w + bv.w;
    *(float4*)&o[i] = v;
}

// ---------------- launch ----------------
extern "C" void kernel_launch(void* const* d_in, const int* in_sizes, int n_in,
                              void* d_out, int out_size)
{
    (void)in_sizes; (void)n_in; (void)out_size;
    const float* x     = (const float*)d_in[0];
    const float* Wq    = (const float*)d_in[1];
    const float* bq    = (const float*)d_in[2];
    const float* Wk    = (const float*)d_in[3];
    const float* bk    = (const float*)d_in[4];
    const float* Wv    = (const float*)d_in[5];
    const float* bv    = (const float*)d_in[6];
    const float* Wo    = (const float*)d_in[7];
    const float* bo    = (const float*)d_in[8];
    const float* ln1g  = (const float*)d_in[9];
    const float* ln1b  = (const float*)d_in[10];
    const float* gateW = (const float*)d_in[11];
    const float* gateb = (const float*)d_in[12];
    const float* W1e   = (const float*)d_in[13];
    const float* b1e   = (const float*)d_in[14];
    const float* W2e   = (const float*)d_in[15];
    const float* b2e   = (const float*)d_in[16];
    const float* Wd    = (const float*)d_in[17];
    const float* bd    = (const float*)d_in[18];
    const float* ln2g  = (const float*)d_in[19];
    const float* ln2b  = (const float*)d_in[20];

    float* out = (float*)d_out;
    float* gate_out = out + (size_t)SEQ * DM;

    float *pq, *pk, *pv, *pattno, *ptmp, *px1, *pmoe;
    cudaGetSymbolAddress((void**)&pq, g_q);
    cudaGetSymbolAddress((void**)&pk, g_k);
    cudaGetSymbolAddress((void**)&pv, g_v);
    cudaGetSymbolAddress((void**)&pattno, g_attno);
    cudaGetSymbolAddress((void**)&ptmp, g_tmp);
    cudaGetSymbolAddress((void**)&px1, g_x1);
    cudaGetSymbolAddress((void**)&pmoe, g_moe);

    dim3 gemm_grid(DM / BN, SEQ / BM);   // (12, 32)

    reset_kernel<<<1, 32>>>();

    // QKV projections (fp32 — gating-critical path; q pre-scaled by 1/sqrt(64))
    gemm_kernel<<<gemm_grid, 256>>>(x, Wq, bq, pq, SEQ, DM, DM, nullptr, 0.125f, 1);
    gemm_kernel<<<gemm_grid, 256>>>(x, Wk, bk, pk, SEQ, DM, DM, nullptr, 1.0f, 1);
    gemm_kernel<<<gemm_grid, 256>>>(x, Wv, bv, pv, SEQ, DM, DM, nullptr, 1.0f, 1);

    // sliding-window attention (fp32)
    attn_kernel<<<dim3(SEQ / 64, NH), 256>>>(pattno);

    // Wo projection + residual(hidden) -> LN1 -> x1 (fp32)
    gemm_kernel<<<gemm_grid, 256>>>(pattno, Wo, bo, ptmp, SEQ, DM, DM, x, 1.0f, 2);
    ln_kernel<<<SEQ, 256>>>(ptmp, ln1g, ln1b, px1);

    // gating (fp32-exact; writes gate_weights output + expert lists)
    gating_kernel<<<SEQ, 256>>>(px1, gateW, gateb, gate_out);

    // MoE expert FFN (tf32 tensor cores, grouped sparse top-2)
    mma_moe_gemm1<<<dim3(FF / BN, SEQ / BM, NE), 256>>>(px1, W1e, b1e);
    mma_moe_gemm2<<<dim3(DM / BN, SEQ / BM, NE), 256>>>(W2e, b2e);
    combine_kernel<<<SEQ, 192>>>();

    // Wd projection (tf32) + residual(x1) -> LN2 -> layer_output
    mma_gemm_res<<<gemm_grid, 256>>>(pmoe, Wd, bd, ptmp, px1, SEQ, DM, DM);
    ln_kernel<<<SEQ, 256>>>(ptmp, ln2g, ln2b, out);
}

// round 7
// speedup vs baseline: 1.5866x; 1.0000x over previous
#include <cuda_runtime.h>
#include <math.h>

#define SEQ 4096
#define DM  768
#define NH  12
#define DH  64
#define FF  3072
#define NE  7
#define WIN 256
#define CAP 4096

// ---------------- scratch (static device globals; no allocation) ----------------
__device__ float g_q[NH * SEQ * DH];
__device__ float g_k[NH * SEQ * DH];
__device__ float g_v[NH * SEQ * DH];
__device__ float g_attno[SEQ * DM];
__device__ float g_tmp[SEQ * DM];
__device__ float g_x1[SEQ * DM];
__device__ float g_moe[SEQ * DM];
__device__ float g_h[NE * CAP * FF];     // 352 MB
__device__ float g_eo[NE * CAP * DM];    // 88 MB
__device__ int   g_cnt[NE];
__device__ int   g_tok[NE * CAP];
__device__ float g_wl[NE * CAP];
__device__ int   g_pos[SEQ * 2];

// ---------------- reset ----------------
__global__ void reset_kernel() {
    if (threadIdx.x < NE) g_cnt[threadIdx.x] = 0;
}

// ======================================================================
// fp32 SIMT GEMM (kept for the gating-critical path: QKV, Wo)
// ======================================================================
#define BM 128
#define BN 64
#define BK 16

__global__ __launch_bounds__(256) void gemm_kernel(
    const float* __restrict__ A, const float* __restrict__ B,
    const float* __restrict__ bias, float* __restrict__ C,
    int M, int N, int K, const float* __restrict__ residual,
    float scale, int mode)
{
    __shared__ float As[BK][BM];
    __shared__ float Bs[BK][BN];
    int tid = threadIdx.x;
    int m0 = blockIdx.y * BM;
    int n0 = blockIdx.x * BN;
    int rg = tid >> 4;
    int cg = tid & 15;
    int ar = tid >> 2;
    int ac = (tid & 3) << 2;
    int br = tid >> 4;
    int bc = (tid & 15) << 2;

    float acc[8][4];
#pragma unroll
    for (int i = 0; i < 8; i++)
#pragma unroll
        for (int j = 0; j < 4; j++) acc[i][j] = 0.f;

    for (int k0 = 0; k0 < K; k0 += BK) {
#pragma unroll
        for (int it = 0; it < 2; it++) {
            int r = ar + it * 64;
            float4 av = *(const float4*)&A[(size_t)(m0 + r) * K + k0 + ac];
            As[ac + 0][r] = av.x;
            As[ac + 1][r] = av.y;
            As[ac + 2][r] = av.z;
            As[ac + 3][r] = av.w;
        }
        float4 bv = *(const float4*)&B[(size_t)(k0 + br) * N + n0 + bc];
        *(float4*)&Bs[br][bc] = bv;
        __syncthreads();
#pragma unroll
        for (int k = 0; k < BK; k++) {
            float4 a0 = *(const float4*)&As[k][rg * 8];
            float4 a1 = *(const float4*)&As[k][rg * 8 + 4];
            float4 b0 = *(const float4*)&Bs[k][cg * 4];
            float a[8] = {a0.x, a0.y, a0.z, a0.w, a1.x, a1.y, a1.z, a1.w};
            float b[4] = {b0.x, b0.y, b0.z, b0.w};
#pragma unroll
            for (int i = 0; i < 8; i++)
#pragma unroll
                for (int j = 0; j < 4; j++) acc[i][j] += a[i] * b[j];
        }
        __syncthreads();
    }

#pragma unroll
    for (int i = 0; i < 8; i++) {
        int row = m0 + rg * 8 + i;
#pragma unroll
        for (int j = 0; j < 4; j++) {
            int col = n0 + cg * 4 + j;
            float v = acc[i][j] + bias[col];
            if (mode == 0) {
                C[(size_t)row * N + col] = v;
            } else if (mode == 1) {
                C[((size_t)(col >> 6) * M + row) * 64 + (col & 63)] = v * scale;
            } else {
                C[(size_t)row * N + col] = v + residual[(size_t)row * N + col];
            }
        }
    }
}

// ======================================================================
// tf32 tensor-core GEMM machinery (mma.sync.m16n8k8)
// BM=128, BN=64, BK=16, 256 threads = 8 warps in 4x2, warp tile 32x32.
// ======================================================================
#define APADM 136   // BM + 8 : conflict-free fragment loads
#define APADN 72    // BN + 8

__device__ __forceinline__ unsigned f2tf(float f) {
    unsigned u;
    asm("cvt.rna.tf32.f32 %0, %1;" : "=r"(u) : "f"(f));
    return u;
}

__device__ __forceinline__ void mma_tf32(float* c, const unsigned* a, const unsigned* b) {
    asm volatile(
        "mma.sync.aligned.m16n8k8.row.col.f32.tf32.tf32.f32 "
        "{%0,%1,%2,%3}, {%4,%5,%6,%7}, {%8,%9}, {%0,%1,%2,%3};"
        : "+f"(c[0]), "+f"(c[1]), "+f"(c[2]), "+f"(c[3])
        : "r"(a[0]), "r"(a[1]), "r"(a[2]), "r"(a[3]),
          "r"(b[0]), "r"(b[1]));
}

// shared mainloop body: fills acc[2][4][4] for this block/warp
// A_loader: lambda-free — implemented via macro parameters in each kernel
#define MMA_DECLS()                                                        \
    __shared__ unsigned As[BK][APADM];                                     \
    __shared__ unsigned Bs[BK][APADN];                                     \
    int tid = threadIdx.x;                                                 \
    int ar = tid >> 2, ac = (tid & 3) << 2;                                \
    int br = tid >> 4, bc = (tid & 15) << 2;                               \
    int w = tid >> 5, lane = tid & 31;                                     \
    int m0w = (w >> 1) * 32, n0w = (w & 1) * 32;                           \
    int g = lane >> 2, t = lane & 3;                                       \
    float acc[2][4][4];                                                    \
    _Pragma("unroll")                                                      \
    for (int mi = 0; mi < 2; mi++)                                         \
        _Pragma("unroll")                                                  \
        for (int ni = 0; ni < 4; ni++)                                     \
            _Pragma("unroll")                                              \
            for (int j = 0; j < 4; j++) acc[mi][ni][j] = 0.f;

#define MMA_COMPUTE()                                                      \
    __syncthreads();                                                       \
    _Pragma("unroll")                                                      \
    for (int kk = 0; kk < BK; kk += 8) {                                   \
        unsigned afr[2][4], bfr[4][2];                                     \
        _Pragma("unroll")                                                  \
        for (int mi = 0; mi < 2; mi++) {                                   \
            int mb = m0w + mi * 16 + g;                                    \
            afr[mi][0] = As[kk + t][mb];                                   \
            afr[mi][1] = As[kk + t][mb + 8];                               \
            afr[mi][2] = As[kk + t + 4][mb];                               \
            afr[mi][3] = As[kk + t + 4][mb + 8];                           \
        }                                                                  \
        _Pragma("unroll")                                                  \
        for (int ni = 0; ni < 4; ni++) {                                   \
            int nb = n0w + ni * 8 + g;                                     \
            bfr[ni][0] = Bs[kk + t][nb];                                   \
            bfr[ni][1] = Bs[kk + t + 4][nb];                               \
        }                                                                  \
        _Pragma("unroll")                                                  \
        for (int mi = 0; mi < 2; mi++)                                     \
            _Pragma("unroll")                                              \
            for (int ni = 0; ni < 4; ni++)                                 \
                mma_tf32(acc[mi][ni], afr[mi], bfr[ni]);                   \
    }                                                                      \
    __syncthreads();

// ---------------- MoE GEMM 1 (tf32): gather + GELU ----------------
__global__ __launch_bounds__(256) void mma_moe_gemm1(
    const float* __restrict__ X, const float* __restrict__ W1,
    const float* __restrict__ b1)
{
    int e = blockIdx.z;
    int M = g_cnt[e];
    int m0 = blockIdx.y * BM;
    if (m0 >= M) return;
    const float* B = W1 + (size_t)e * DM * FF;
    const float* bias = b1 + (size_t)e * FF;
    float* C = g_h + (size_t)e * CAP * FF;
    const int* tl = g_tok + e * CAP;
    int n0 = blockIdx.x * BN;

    MMA_DECLS();

    for (int k0 = 0; k0 < DM; k0 += BK) {
#pragma unroll
        for (int it = 0; it < 2; it++) {
            int r = ar + it * 64;
            int grow = m0 + r;
            float4 av = make_float4(0.f, 0.f, 0.f, 0.f);
            if (grow < M) {
                int trow = tl[grow];
                av = *(const float4*)&X[(size_t)trow * DM + k0 + ac];
            }
            As[ac + 0][r] = f2tf(av.x);
            As[ac + 1][r] = f2tf(av.y);
            As[ac + 2][r] = f2tf(av.z);
            As[ac + 3][r] = f2tf(av.w);
        }
        {
            float4 bv = *(const float4*)&B[(size_t)(k0 + br) * FF + n0 + bc];
            Bs[br][bc + 0] = f2tf(bv.x);
            Bs[br][bc + 1] = f2tf(bv.y);
            Bs[br][bc + 2] = f2tf(bv.z);
            Bs[br][bc + 3] = f2tf(bv.w);
        }
        MMA_COMPUTE();
    }

#pragma unroll
    for (int mi = 0; mi < 2; mi++) {
#pragma unroll
        for (int ni = 0; ni < 4; ni++) {
            int col = n0 + n0w + ni * 8 + 2 * t;
            float bv0 = bias[col], bv1 = bias[col + 1];
#pragma unroll
            for (int half = 0; half < 2; half++) {
                int row = m0 + m0w + mi * 16 + g + half * 8;
                if (row >= M) continue;
                float v0 = acc[mi][ni][half * 2 + 0] + bv0;
                float v1 = acc[mi][ni][half * 2 + 1] + bv1;
                v0 = 0.5f * v0 * (1.f + erff(v0 * 0.70710678118654752f));
                v1 = 0.5f * v1 * (1.f + erff(v1 * 0.70710678118654752f));
                C[(size_t)row * FF + col]     = v0;
                C[(size_t)row * FF + col + 1] = v1;
            }
        }
    }
}

// ---------------- MoE GEMM 2 (tf32): * gate weight ----------------
__global__ __launch_bounds__(256) void mma_moe_gemm2(
    const float* __restrict__ W2, const float* __restrict__ b2)
{
    int e = blockIdx.z;
    int M = g_cnt[e];
    int m0 = blockIdx.y * BM;
    if (m0 >= M) return;
    const float* A = g_h + (size_t)e * CAP * FF;
    const float* B = W2 + (size_t)e * FF * DM;
    const float* bias = b2 + (size_t)e * DM;
    const float* wl = g_wl + e * CAP;
    float* C = g_eo + (size_t)e * CAP * DM;
    int n0 = blockIdx.x * BN;

    MMA_DECLS();

    for (int k0 = 0; k0 < FF; k0 += BK) {
#pragma unroll
        for (int it = 0; it < 2; it++) {
            int r = ar + it * 64;
            int grow = m0 + r;
            float4 av = make_float4(0.f, 0.f, 0.f, 0.f);
            if (grow < M) av = *(const float4*)&A[(size_t)grow * FF + k0 + ac];
            As[ac + 0][r] = f2tf(av.x);
            As[ac + 1][r] = f2tf(av.y);
            As[ac + 2][r] = f2tf(av.z);
            As[ac + 3][r] = f2tf(av.w);
        }
        {
            float4 bv = *(const float4*)&B[(size_t)(k0 + br) * DM + n0 + bc];
            Bs[br][bc + 0] = f2tf(bv.x);
            Bs[br][bc + 1] = f2tf(bv.y);
            Bs[br][bc + 2] = f2tf(bv.z);
            Bs[br][bc + 3] = f2tf(bv.w);
        }
        MMA_COMPUTE();
    }

#pragma unroll
    for (int mi = 0; mi < 2; mi++) {
#pragma unroll
        for (int ni = 0; ni < 4; ni++) {
            int col = n0 + n0w + ni * 8 + 2 * t;
            float bv0 = bias[col], bv1 = bias[col + 1];
#pragma unroll
            for (int half = 0; half < 2; half++) {
                int row = m0 + m0w + mi * 16 + g + half * 8;
                if (row >= M) continue;
                float wv = wl[row];
                C[(size_t)row * DM + col]     = (acc[mi][ni][half * 2 + 0] + bv0) * wv;
                C[(size_t)row * DM + col + 1] = (acc[mi][ni][half * 2 + 1] + bv1) * wv;
            }
        }
    }
}

// ---------------- Wd GEMM (tf32): + bias + residual ----------------
__global__ __launch_bounds__(256) void mma_gemm_res(
    const float* __restrict__ A, const float* __restrict__ B,
    const float* __restrict__ bias, float* __restrict__ C,
    const float* __restrict__ R, int M, int N, int K)
{
    int m0 = blockIdx.y * BM;
    int n0 = blockIdx.x * BN;

    MMA_DECLS();

    for (int k0 = 0; k0 < K; k0 += BK) {
#pragma unroll
        for (int it = 0; it < 2; it++) {
            int r = ar + it * 64;
            float4 av = *(const float4*)&A[(size_t)(m0 + r) * K + k0 + ac];
            As[ac + 0][r] = f2tf(av.x);
            As[ac + 1][r] = f2tf(av.y);
            As[ac + 2][r] = f2tf(av.z);
            As[ac + 3][r] = f2tf(av.w);
        }
        {
            float4 bv = *(const float4*)&B[(size_t)(k0 + br) * N + n0 + bc];
            Bs[br][bc + 0] = f2tf(bv.x);
            Bs[br][bc + 1] = f2tf(bv.y);
            Bs[br][bc + 2] = f2tf(bv.z);
            Bs[br][bc + 3] = f2tf(bv.w);
        }
        MMA_COMPUTE();
    }

#pragma unroll
    for (int mi = 0; mi < 2; mi++) {
#pragma unroll
        for (int ni = 0; ni < 4; ni++) {
            int col = n0 + n0w + ni * 8 + 2 * t;
            float bv0 = bias[col], bv1 = bias[col + 1];
#pragma unroll
            for (int half = 0; half < 2; half++) {
                int row = m0 + m0w + mi * 16 + g + half * 8;
                size_t idx = (size_t)row * N + col;
                C[idx]     = acc[mi][ni][half * 2 + 0] + bv0 + R[idx];
                C[idx + 1] = acc[mi][ni][half * 2 + 1] + bv1 + R[idx + 1];
            }
        }
    }
}

// ---------------- fused sliding-window attention ----------------
#define APAD 68
__global__ __launch_bounds__(256) void attn_kernel(float* __restrict__ out)
{
    __shared__ float Qs[64][APAD];
    __shared__ float Ks[32][APAD];
    __shared__ float Vs[32][APAD];
    __shared__ float Ss[64][33];
    __shared__ float mS[64], lS[64], cS[64];

    int h = blockIdx.y;
    int q0 = blockIdx.x * 64;
    int tid = threadIdx.x;
    int q = tid & 63;
    int kg = tid >> 6;
    int dp = tid >> 6;

    const float* qhead = g_q + (size_t)h * SEQ * DH;
    const float* khead = g_k + (size_t)h * SEQ * DH;
    const float* vhead = g_v + (size_t)h * SEQ * DH;

#pragma unroll
    for (int i = 0; i < 4; i++) {
        int idx = tid + i * 256;
        int r = idx >> 4;
        int c = (idx & 15) << 2;
        float4 v = *(const float4*)&qhead[(size_t)(q0 + r) * DH + c];
        *(float4*)&Qs[r][c] = v;
    }
    if (tid < 64) { mS[tid] = -1e9f; lS[tid] = 0.f; }

    float acc[16];
#pragma unroll
    for (int i = 0; i < 16; i++) acc[i] = 0.f;
    __syncthreads();

    for (int kt = 0; kt < 18; kt++) {
        int kbase = q0 - 256 + kt * 32;
        if (kbase + 31 < 0 || kbase >= SEQ) continue;

#pragma unroll
        for (int i = 0; i < 2; i++) {
            int idx = tid + i * 256;
            int r = idx >> 4;
            int c = (idx & 15) << 2;
            int kpos = kbase + r;
            float4 kv = make_float4(0.f, 0.f, 0.f, 0.f);
            float4 vv = kv;
            if (kpos >= 0 && kpos < SEQ) {
                kv = *(const float4*)&khead[(size_t)kpos * DH + c];
                vv = *(const float4*)&vhead[(size_t)kpos * DH + c];
            }
            *(float4*)&Ks[r][c] = kv;
            *(float4*)&Vs[r][c] = vv;
        }
        __syncthreads();

        float s[8];
#pragma unroll
        for (int j = 0; j < 8; j++) s[j] = 0.f;
#pragma unroll
        for (int d = 0; d < 64; d += 4) {
            float4 q4 = *(const float4*)&Qs[q][d];
#pragma unroll
            for (int j = 0; j < 8; j++) {
                float4 k4 = *(const float4*)&Ks[kg * 8 + j][d];
                s[j] += q4.x * k4.x + q4.y * k4.y + q4.z * k4.z + q4.w * k4.w;
            }
        }
        int qpos = q0 + q;
#pragma unroll
        for (int j = 0; j < 8; j++) {
            int kpos = kbase + kg * 8 + j;
            bool valid = (kpos >= 0) && (kpos < SEQ) &&
                         (kpos >= qpos - WIN) && (kpos <= qpos + WIN);
            Ss[q][kg * 8 + j] = valid ? s[j] : -1e9f;
        }
        __syncthreads();

        if (tid < 64) {
            int r = tid;
            float mold = mS[r];
            float tmax = -1e9f;
#pragma unroll
            for (int kk = 0; kk < 32; kk++) tmax = fmaxf(tmax, Ss[r][kk]);
            float mnew = fmaxf(mold, tmax);
            float corr = __expf(mold - mnew);
            float sum = 0.f;
#pragma unroll
            for (int kk = 0; kk < 32; kk++) {
                float p = __expf(Ss[r][kk] - mnew);
                Ss[r][kk] = p;
                sum += p;
            }
            lS[r] = lS[r] * corr + sum;
            mS[r] = mnew;
            cS[r] = corr;
        }
        __syncthreads();

        float corr = cS[q];
#pragma unroll
        for (int i = 0; i < 16; i++) acc[i] *= corr;
#pragma unroll
        for (int kk = 0; kk < 32; kk++) {
            float p = Ss[q][kk];
#pragma unroll
            for (int i4 = 0; i4 < 4; i4++) {
                float4 v4 = *(const float4*)&Vs[kk][dp * 16 + i4 * 4];
                acc[i4 * 4 + 0] += p * v4.x;
                acc[i4 * 4 + 1] += p * v4.y;
                acc[i4 * 4 + 2] += p * v4.z;
                acc[i4 * 4 + 3] += p * v4.w;
            }
        }
        __syncthreads();
    }

    float inv = 1.f / lS[q];
    float* o = out + (size_t)(q0 + q) * DM + h * DH + dp * 16;
#pragma unroll
    for (int i4 = 0; i4 < 4; i4++) {
        float4 v;
        v.x = acc[i4 * 4 + 0] * inv;
        v.y = acc[i4 * 4 + 1] * inv;
        v.z = acc[i4 * 4 + 2] * inv;
        v.w = acc[i4 * 4 + 3] * inv;
        *(float4*)&o[i4 * 4] = v;
    }
}

// ---------------- layer norm (row-wise) ----------------
__global__ __launch_bounds__(256) void ln_kernel(
    const float* __restrict__ in, const float* __restrict__ g,
    const float* __restrict__ b, float* __restrict__ out)
{
    __shared__ float rs[8], rs2[8];
    int row = blockIdx.x;
    int tid = threadIdx.x;
    const float* x = in + (size_t)row * DM;
    float vals[3];
    float s = 0.f, s2 = 0.f;
#pragma unroll
    for (int i = 0; i < 3; i++) {
        float v = x[tid + i * 256];
        vals[i] = v;
        s += v;
        s2 += v * v;
    }
    int lane = tid & 31, w = tid >> 5;
#pragma unroll
    for (int o = 16; o; o >>= 1) {
        s += __shfl_down_sync(0xffffffffu, s, o);
        s2 += __shfl_down_sync(0xffffffffu, s2, o);
    }
    if (lane == 0) { rs[w] = s; rs2[w] = s2; }
    __syncthreads();
    if (tid == 0) {
        float a = 0.f, c = 0.f;
#pragma unroll
        for (int i = 0; i < 8; i++) { a += rs[i]; c += rs2[i]; }
        rs[0] = a;
        rs2[0] = c;
    }
    __syncthreads();
    float mean = rs[0] * (1.f / DM);
    float var = rs2[0] * (1.f / DM) - mean * mean;
    float rstd = rsqrtf(var + 1e-5f);
    float* o = out + (size_t)row * DM;
#pragma unroll
    for (int i = 0; i < 3; i++) {
        int col = tid + i * 256;
        o[col] = (vals[i] - mean) * rstd * g[col] + b[col];
    }
}

// ---------------- gating: logits, top-2, softmax, expert lists ----------------
__global__ __launch_bounds__(256) void gating_kernel(
    const float* __restrict__ x1, const float* __restrict__ gW,
    const float* __restrict__ gb, float* __restrict__ gate_out)
{
    __shared__ float xs[DM];
    __shared__ float lg[8];
    int row = blockIdx.x;
    int tid = threadIdx.x;
    for (int i = tid; i < DM; i += 256) xs[i] = x1[(size_t)row * DM + i];
    __syncthreads();
    int w = tid >> 5, lane = tid & 31;
    if (w < NE) {
        float p = 0.f;
        for (int d = lane; d < DM; d += 32) p += xs[d] * gW[d * NE + w];
#pragma unroll
        for (int o = 16; o; o >>= 1) p += __shfl_down_sync(0xffffffffu, p, o);
        if (lane == 0) lg[w] = p + gb[w];
    }
    __syncthreads();
    if (tid == 0) {
        int e1 = 0;
        float v1 = lg[0];
        for (int e = 1; e < NE; e++)
            if (lg[e] > v1) { v1 = lg[e]; e1 = e; }
        int e2 = -1;
        float v2 = -1e30f;
        for (int e = 0; e < NE; e++) {
            if (e == e1) continue;
            if (lg[e] > v2) { v2 = lg[e]; e2 = e; }
        }
        float z = expf(v2 - v1);
        float w1 = 1.f / (1.f + z);
        float w2 = z / (1.f + z);
        float* go = gate_out + (size_t)row * NE;
#pragma unroll
        for (int e = 0; e < NE; e++) go[e] = 0.f;
        go[e1] = w1;
        go[e2] = w2;
        int s1 = atomicAdd(&g_cnt[e1], 1);
        g_tok[e1 * CAP + s1] = row;
        g_wl[e1 * CAP + s1] = w1;
        g_pos[row * 2 + 0] = e1 * CAP + s1;
        int s2 = atomicAdd(&g_cnt[e2], 1);
        g_tok[e2 * CAP + s2] = row;
        g_wl[e2 * CAP + s2] = w2;
        g_pos[row * 2 + 1] = e2 * CAP + s2;
    }
}

// ---------------- combine two expert outputs per token ----------------
__global__ __launch_bounds__(192) void combine_kernel()
{
    int t = blockIdx.x;
    int p0 = g_pos[t * 2 + 0];
    int p1 = g_pos[t * 2 + 1];
    const float* a = g_eo + (size_t)p0 * DM;
    const float* b = g_eo + (size_t)p1 * DM;
    float* o = g_moe + (size_t)t * DM;
    int i = threadIdx.x * 4;
    float4 av = *(const float4*)&a[i];
    float4 bv = *(const float4*)&b[i];
    float4 v;
    v.x = av.x + bv.x;
    v.y = av.y + bv.y;
    v.z = av.z + bv.z;
    v.w = av.w + bv.w;
    *(float4*)&o[i] = v;
}

// ---------------- launch ----------------
extern "C" void kernel_launch(void* const* d_in, const int* in_sizes, int n_in,
                              void* d_out, int out_size)
{
    (void)in_sizes; (void)n_in; (void)out_size;
    const float* x     = (const float*)d_in[0];
    const float* Wq    = (const float*)d_in[1];
    const float* bq    = (const float*)d_in[2];
    const float* Wk    = (const float*)d_in[3];
    const float* bk    = (const float*)d_in[4];
    const float* Wv    = (const float*)d_in[5];
    const float* bv    = (const float*)d_in[6];
    const float* Wo    = (const float*)d_in[7];
    const float* bo    = (const float*)d_in[8];
    const float* ln1g  = (const float*)d_in[9];
    const float* ln1b  = (const float*)d_in[10];
    const float* gateW = (const float*)d_in[11];
    const float* gateb = (const float*)d_in[12];
    const float* W1e   = (const float*)d_in[13];
    const float* b1e   = (const float*)d_in[14];
    const float* W2e   = (const float*)d_in[15];
    const float* b2e   = (const float*)d_in[16];
    const float* Wd    = (const float*)d_in[17];
    const float* bd    = (const float*)d_in[18];
    const float* ln2g  = (const float*)d_in[19];
    const float* ln2b  = (const float*)d_in[20];

    float* out = (float*)d_out;
    float* gate_out = out + (size_t)SEQ * DM;

    float *pq, *pk, *pv, *pattno, *ptmp, *px1, *pmoe;
    cudaGetSymbolAddress((void**)&pq, g_q);
    cudaGetSymbolAddress((void**)&pk, g_k);
    cudaGetSymbolAddress((void**)&pv, g_v);
    cudaGetSymbolAddress((void**)&pattno, g_attno);
    cudaGetSymbolAddress((void**)&ptmp, g_tmp);
    cudaGetSymbolAddress((void**)&px1, g_x1);
    cudaGetSymbolAddress((void**)&pmoe, g_moe);

    dim3 gemm_grid(DM / BN, SEQ / BM);   // (12, 32)

    reset_kernel<<<1, 32>>>();

    // QKV projections (fp32 — gating-critical path; q pre-scaled by 1/sqrt(64))
    gemm_kernel<<<gemm_grid, 256>>>(x, Wq, bq, pq, SEQ, DM, DM, nullptr, 0.125f, 1);
    gemm_kernel<<<gemm_grid, 256>>>(x, Wk, bk, pk, SEQ, DM, DM, nullptr, 1.0f, 1);
    gemm_kernel<<<gemm_grid, 256>>>(x, Wv, bv, pv, SEQ, DM, DM, nullptr, 1.0f, 1);

    // sliding-window attention (fp32)
    attn_kernel<<<dim3(SEQ / 64, NH), 256>>>(pattno);

    // Wo projection + residual(hidden) -> LN1 -> x1 (fp32)
    gemm_kernel<<<gemm_grid, 256>>>(pattno, Wo, bo, ptmp, SEQ, DM, DM, x, 1.0f, 2);
    ln_kernel<<<SEQ, 256>>>(ptmp, ln1g, ln1b, px1);

    // gating (fp32-exact; writes gate_weights output + expert lists)
    gating_kernel<<<SEQ, 256>>>(px1, gateW, gateb, gate_out);

    // MoE expert FFN (tf32 tensor cores, grouped sparse top-2)
    mma_moe_gemm1<<<dim3(FF / BN, SEQ / BM, NE), 256>>>(px1, W1e, b1e);
    mma_moe_gemm2<<<dim3(DM / BN, SEQ / BM, NE), 256>>>(W2e, b2e);
    combine_kernel<<<SEQ, 192>>>();

    // Wd projection (tf32) + residual(x1) -> LN2 -> layer_output
    mma_gemm_res<<<gemm_grid, 256>>>(pmoe, Wd, bd, ptmp, px1, SEQ, DM, DM);
    ln_kernel<<<SEQ, 256>>>(ptmp, ln2g, ln2b, out);
}